// round 7
// baseline (speedup 1.0000x reference)
#include <cuda_runtime.h>
#include <math.h>
#include <stdint.h>

#define LL 2048
#define NROWS 8192   // B*L

// ---------------- scratch (device globals; no runtime allocation) ----------------
static __device__ float g_zx [NROWS * 3088]; // zxbcdt
static __device__ float g_X  [NROWS * 1024]; // silu(conv) x part
static __device__ float g_Bm [NROWS * 512];
static __device__ float g_Cm [NROWS * 512];
static __device__ float g_dt [NROWS * 16];
static __device__ float g_dec[NROWS * 16];
static __device__ float g_yp [512 * LL * 64]; // y partials per (b,head,nblock16)
static __device__ float g_g  [NROWS * 1024]; // gated
static __device__ float g_res[NROWS * 512];  // pre-norm residual

// ---------------- tf32 helpers ----------------------------------------------------
__device__ __forceinline__ uint32_t f2tf32(float v) {
    uint32_t r;
    asm("cvt.rna.tf32.f32 %0, %1;" : "=r"(r) : "f"(v));
    return r;
}
__device__ __forceinline__ void split_tf32(float v, float& hi, float& lo) {
    uint32_t h = f2tf32(v);
    hi = __uint_as_float(h);
    float l = v - hi;                 // exact in fp32
    lo = __uint_as_float(f2tf32(l));
}
__device__ __forceinline__ void mma_tf32(float d[4],
                                         uint32_t a0, uint32_t a1, uint32_t a2, uint32_t a3,
                                         uint32_t b0, uint32_t b1) {
    asm volatile(
        "mma.sync.aligned.m16n8k8.row.col.f32.tf32.tf32.f32 "
        "{%0,%1,%2,%3}, {%4,%5,%6,%7}, {%8,%9}, {%0,%1,%2,%3};"
        : "+f"(d[0]), "+f"(d[1]), "+f"(d[2]), "+f"(d[3])
        : "r"(a0), "r"(a1), "r"(a2), "r"(a3), "r"(b0), "r"(b1));
}

// ---------------- cp.async helpers -------------------------------------------------
__device__ __forceinline__ void cp16(void* smem, const void* g) {
    uint32_t s = (uint32_t)__cvta_generic_to_shared(smem);
    asm volatile("cp.async.cg.shared.global [%0], [%1], 16;" :: "r"(s), "l"(g) : "memory");
}
__device__ __forceinline__ void cp4(void* smem, const void* g) {
    uint32_t s = (uint32_t)__cvta_generic_to_shared(smem);
    asm volatile("cp.async.ca.shared.global [%0], [%1], 4;" :: "r"(s), "l"(g) : "memory");
}
#define CP_COMMIT() asm volatile("cp.async.commit_group;" ::: "memory")
#define CP_WAIT13() asm volatile("cp.async.wait_group 13;" ::: "memory")

// ---------------- TF32 tensor-core GEMM: C = A(MxK) @ B(KxN) [+ Res] --------------
template<int Nv, int Kv, bool GUARD, bool ADDRES>
__device__ __forceinline__ void gemm_tf32_body(const float* __restrict__ A,
                                               const float* __restrict__ Bw,
                                               float* __restrict__ C,
                                               const float* __restrict__ Res)
{
    __shared__ __align__(16) float sA[2][2][8][136]; // [buf][hi/lo][k][row]
    __shared__ __align__(16) float sB[2][2][8][136]; // [buf][hi/lo][k][col]

    const int tid   = threadIdx.x;
    const int warp  = tid >> 5;
    const int lane  = tid & 31;
    const int gid   = lane >> 2;   // 0..7
    const int tig   = lane & 3;    // 0..3
    const int warpM = warp & 1;    // 0..1 (64 rows each)
    const int warpN = warp >> 1;   // 0..3 (32 cols each)

    const int aRow = tid >> 1;         // 0..127
    const int aCol = (tid & 1) * 4;    // 0 or 4
    const int bRow = tid >> 5;         // 0..7
    const int bCol = (tid & 31) * 4;   // 0..124

    const int nbase = blockIdx.x * 128;
    const int mbase = blockIdx.y * 128;
    const float* Ap = A + (size_t)(mbase + aRow) * Kv + aCol;
    const float* Bp = Bw + (size_t)bRow * Nv + nbase + bCol;
    const bool  bOK = (!GUARD) || (nbase + bCol + 3 < Nv);

    float acc[4][4][4];
#pragma unroll
    for (int mt = 0; mt < 4; mt++)
#pragma unroll
        for (int nt = 0; nt < 4; nt++)
#pragma unroll
            for (int i = 0; i < 4; i++) acc[mt][nt][i] = 0.f;

    {
        float4 av = *(const float4*)Ap;
        float4 bv = bOK ? *(const float4*)Bp : make_float4(0.f,0.f,0.f,0.f);
        float h, l;
        split_tf32(av.x, h, l); sA[0][0][aCol+0][aRow] = h; sA[0][1][aCol+0][aRow] = l;
        split_tf32(av.y, h, l); sA[0][0][aCol+1][aRow] = h; sA[0][1][aCol+1][aRow] = l;
        split_tf32(av.z, h, l); sA[0][0][aCol+2][aRow] = h; sA[0][1][aCol+2][aRow] = l;
        split_tf32(av.w, h, l); sA[0][0][aCol+3][aRow] = h; sA[0][1][aCol+3][aRow] = l;
        float4 bh, bl;
        split_tf32(bv.x, bh.x, bl.x); split_tf32(bv.y, bh.y, bl.y);
        split_tf32(bv.z, bh.z, bl.z); split_tf32(bv.w, bh.w, bl.w);
        *(float4*)&sB[0][0][bRow][bCol] = bh;
        *(float4*)&sB[0][1][bRow][bCol] = bl;
    }
    __syncthreads();

    const int NK = Kv / 8;
    for (int ks = 0; ks < NK; ks++) {
        const int buf = ks & 1;
        float4 av, bv;
        const bool hasNext = (ks + 1 < NK);
        if (hasNext) {
            av = *(const float4*)(Ap + (ks + 1) * 8);
            bv = bOK ? *(const float4*)(Bp + (size_t)(ks + 1) * 8 * Nv)
                     : make_float4(0.f,0.f,0.f,0.f);
        }

        const float (*Ah)[136] = sA[buf][0];
        const float (*Al)[136] = sA[buf][1];
        const float (*Bh)[136] = sB[buf][0];
        const float (*Bl)[136] = sB[buf][1];

        uint32_t ah[4][4], al[4][4], bh[4][2], bl[4][2];
#pragma unroll
        for (int mt = 0; mt < 4; mt++) {
            const int r = warpM * 64 + mt * 16 + gid;
            ah[mt][0] = __float_as_uint(Ah[tig    ][r    ]);
            ah[mt][1] = __float_as_uint(Ah[tig    ][r + 8]);
            ah[mt][2] = __float_as_uint(Ah[tig + 4][r    ]);
            ah[mt][3] = __float_as_uint(Ah[tig + 4][r + 8]);
            al[mt][0] = __float_as_uint(Al[tig    ][r    ]);
            al[mt][1] = __float_as_uint(Al[tig    ][r + 8]);
            al[mt][2] = __float_as_uint(Al[tig + 4][r    ]);
            al[mt][3] = __float_as_uint(Al[tig + 4][r + 8]);
        }
#pragma unroll
        for (int nt = 0; nt < 4; nt++) {
            const int c = warpN * 32 + nt * 8 + gid;
            bh[nt][0] = __float_as_uint(Bh[tig    ][c]);
            bh[nt][1] = __float_as_uint(Bh[tig + 4][c]);
            bl[nt][0] = __float_as_uint(Bl[tig    ][c]);
            bl[nt][1] = __float_as_uint(Bl[tig + 4][c]);
        }

#pragma unroll
        for (int mt = 0; mt < 4; mt++)
#pragma unroll
            for (int nt = 0; nt < 4; nt++) {
                mma_tf32(acc[mt][nt], ah[mt][0], ah[mt][1], ah[mt][2], ah[mt][3],
                         bh[nt][0], bh[nt][1]);
                mma_tf32(acc[mt][nt], ah[mt][0], ah[mt][1], ah[mt][2], ah[mt][3],
                         bl[nt][0], bl[nt][1]);
                mma_tf32(acc[mt][nt], al[mt][0], al[mt][1], al[mt][2], al[mt][3],
                         bh[nt][0], bh[nt][1]);
            }

        if (hasNext) {
            const int nb = buf ^ 1;
            float h, l;
            split_tf32(av.x, h, l); sA[nb][0][aCol+0][aRow] = h; sA[nb][1][aCol+0][aRow] = l;
            split_tf32(av.y, h, l); sA[nb][0][aCol+1][aRow] = h; sA[nb][1][aCol+1][aRow] = l;
            split_tf32(av.z, h, l); sA[nb][0][aCol+2][aRow] = h; sA[nb][1][aCol+2][aRow] = l;
            split_tf32(av.w, h, l); sA[nb][0][aCol+3][aRow] = h; sA[nb][1][aCol+3][aRow] = l;
            float4 bhh, bll;
            split_tf32(bv.x, bhh.x, bll.x); split_tf32(bv.y, bhh.y, bll.y);
            split_tf32(bv.z, bhh.z, bll.z); split_tf32(bv.w, bhh.w, bll.w);
            *(float4*)&sB[nb][0][bRow][bCol] = bhh;
            *(float4*)&sB[nb][1][bRow][bCol] = bll;
        }
        __syncthreads();
    }

#pragma unroll
    for (int mt = 0; mt < 4; mt++) {
        const int row0 = mbase + warpM * 64 + mt * 16 + gid;
#pragma unroll
        for (int nt = 0; nt < 4; nt++) {
            const int col = nbase + warpN * 32 + nt * 8 + tig * 2;
            if (!GUARD || col < Nv) {
                float2 v0 = make_float2(acc[mt][nt][0], acc[mt][nt][1]);
                float2 v1 = make_float2(acc[mt][nt][2], acc[mt][nt][3]);
                if (ADDRES) {
                    float2 r0 = *(const float2*)(Res + (size_t)row0 * Nv + col);
                    float2 r1 = *(const float2*)(Res + (size_t)(row0 + 8) * Nv + col);
                    v0.x += r0.x; v0.y += r0.y; v1.x += r1.x; v1.y += r1.y;
                }
                *(float2*)(C + (size_t)row0 * Nv + col)       = v0;
                *(float2*)(C + (size_t)(row0 + 8) * Nv + col) = v1;
            }
        }
    }
}

__global__ void __launch_bounds__(256) gemm1_kernel(const float* __restrict__ A,
                                                    const float* __restrict__ W)
{
    gemm_tf32_body<3088, 512, true, false>(A, W, g_zx, nullptr);
}

__global__ void __launch_bounds__(256) gemm2_kernel(const float* __restrict__ W,
                                                    const float* __restrict__ Res)
{
    gemm_tf32_body<512, 1024, false, true>(g_g, W, g_res, Res);
}

// ---------------- conv1d (K=4, causal) + bias + silu + split ----------------------
__global__ void conv_kernel(const float* __restrict__ conv_w,
                            const float* __restrict__ conv_b)
{
    const int idx = blockIdx.x * blockDim.x + threadIdx.x; // [0, 8192*2048)
    const int c   = idx & 2047;
    const int row = idx >> 11;
    const int t   = row & (LL - 1);
    float acc = conv_b[c];
#pragma unroll
    for (int k = 0; k < 4; k++) {
        const int tt = t - 3 + k;
        if (tt >= 0)
            acc = fmaf(g_zx[(size_t)(row - (3 - k)) * 3088 + 1024 + c], conv_w[c * 4 + k], acc);
    }
    const float v = acc / (1.f + expf(-acc)); // silu
    if (c < 1024)       g_X [(size_t)row * 1024 + c]          = v;
    else if (c < 1536)  g_Bm[(size_t)row * 512  + (c - 1024)] = v;
    else                g_Cm[(size_t)row * 512  + (c - 1536)] = v;
}

// ---------------- dt / decay ------------------------------------------------------
__global__ void dt_kernel(const float* __restrict__ dt_bias,
                          const float* __restrict__ A_log)
{
    const int idx = blockIdx.x * blockDim.x + threadIdx.x; // [0, 8192*16)
    const int h   = idx & 15;
    const int row = idx >> 4;
    const float x  = g_zx[(size_t)row * 3088 + 3072 + h] + dt_bias[h];
    const float dt = (x > 20.f) ? x : log1pf(expf(x));
    g_dt [idx] = dt;
    g_dec[idx] = expf(-expf(A_log[h]) * dt);
}

// ---------------- selective scan v3 ------------------------------------------------
// Grid: 512 CTAs = (b, head, nblock of 16 states). 128 threads.
// 16-deep cp.async ring, prefetch distance 14, wait_group 13, ONE barrier/iter.
// Iter t: wait(group t) -> barrier -> update h (buffers[t], write sH[t&1])
//         -> prefetch step t+14 into buffer (t+14)&15 -> commit (unconditional)
//         -> y for step t-1 (buffers[(t-1)&15], sH[(t-1)&1]).
// Buffer-reuse safety: (t+14)%16 differs from t%16 and (t-1)%16; every smem
// read/write pair on the same buffer is separated by >=1 __syncthreads.
__global__ void __launch_bounds__(128) scan_kernel()
{
    const int bx = blockIdx.x;
    const int nb = bx & 7;          // 16-state block
    const int bh = bx >> 3;
    const int hh = bh & 15;
    const int bb = bh >> 4;
    const int tid  = threadIdx.x;
    const int n_l  = tid & 15;
    const int pq   = tid >> 4;      // 0..7
    const int pair = tid >> 1;      // 0..63
    const int half = tid & 1;
    const int rY   = pair >> 4;     // 0..3
    const int pY   = pair & 15;     // 0..15

    __shared__ __align__(16) float sB[16][16][4];
    __shared__ __align__(16) float sC[16][16][4];
    __shared__ __align__(16) float sX[16][64];
    __shared__ __align__(16) float sS[16][2];
    __shared__ __align__(16) float sH[2][16][17];

    const float* Bsrc = g_Bm  + (size_t)bb * LL * 512  + nb * 64;
    const float* Csrc = g_Cm  + (size_t)bb * LL * 512  + nb * 64;
    const float* Xsrc = g_X   + (size_t)bb * LL * 1024 + hh * 64;
    const float* Dsrc = g_dec + (size_t)bb * LL * 16   + hh;
    const float* Tsrc = g_dt  + (size_t)bb * LL * 16   + hh;
    float* Ydst = g_yp + (size_t)bx * LL * 64;

    // loader routing: tid 0-15 B, 16-31 C, 32-47 X, 48 dec, 49 dt
    const int li = tid & 15;

    // prologue: issue steps 0..13 as 14 groups
#pragma unroll
    for (int s = 0; s < 14; s++) {
        if (tid < 16)       cp16(&sB[s][li][0], Bsrc + (size_t)s * 512  + li * 4);
        else if (tid < 32)  cp16(&sC[s][li][0], Csrc + (size_t)s * 512  + li * 4);
        else if (tid < 48)  cp16(&sX[s][li * 4], Xsrc + (size_t)s * 1024 + li * 4);
        else if (tid == 48) cp4(&sS[s][0], Dsrc + (size_t)s * 16);
        else if (tid == 49) cp4(&sS[s][1], Tsrc + (size_t)s * 16);
        CP_COMMIT();
    }

    float h0 = 0.f, h1 = 0.f;
    const int p0 = pq * 2;
    const int p1 = p0 + 1;

    for (int t = 0; t < LL; t++) {
        const int cb = t & 15;
        const int hb = t & 1;

        // ---- retire group t, make its data + prev sH visible ----
        CP_WAIT13();
        __syncthreads();

        // ---- state update (step t) ----
        const float4 Bv  = *(const float4*)&sB[cb][n_l][0];
        const float  dec = sS[cb][0];
        const float  dtv = sS[cb][1];
        const float u0 = (Bv.x * sX[cb][ 0 + p0] + Bv.y * sX[cb][16 + p0])
                       + (Bv.z * sX[cb][32 + p0] + Bv.w * sX[cb][48 + p0]);
        const float u1 = (Bv.x * sX[cb][ 0 + p1] + Bv.y * sX[cb][16 + p1])
                       + (Bv.z * sX[cb][32 + p1] + Bv.w * sX[cb][48 + p1]);
        h0 = fmaf(dec, h0, dtv * u0);
        h1 = fmaf(dec, h1, dtv * u1);
        sH[hb][p0][n_l] = h0;
        sH[hb][p1][n_l] = h1;

        // ---- prefetch step t+14 into buffer (t+14)&15 ----
        const int ts = t + 14;
        if (ts < LL) {
            const int sb = ts & 15;
            if (tid < 16)       cp16(&sB[sb][li][0], Bsrc + (size_t)ts * 512  + li * 4);
            else if (tid < 32)  cp16(&sC[sb][li][0], Csrc + (size_t)ts * 512  + li * 4);
            else if (tid < 48)  cp16(&sX[sb][li * 4], Xsrc + (size_t)ts * 1024 + li * 4);
            else if (tid == 48) cp4(&sS[sb][0], Dsrc + (size_t)ts * 16);
            else if (tid == 49) cp4(&sS[sb][1], Tsrc + (size_t)ts * 16);
        }
        CP_COMMIT();   // unconditional: keeps FIFO depth exactly 14

        // ---- y partial for step t-1 ----
        if (t > 0) {
            const int cbp = (t - 1) & 15;
            const int hbp = (t - 1) & 1;
            const float* Cc = &sC[cbp][half * 8][0];
            const float* Hh = &sH[hbp][pY][half * 8];
            float a0 = 0.f, a1 = 0.f;
#pragma unroll
            for (int i = 0; i < 4; i++) {
                a0 = fmaf(Cc[(2 * i    ) * 4 + rY], Hh[2 * i    ], a0);
                a1 = fmaf(Cc[(2 * i + 1) * 4 + rY], Hh[2 * i + 1], a1);
            }
            float acc = a0 + a1;
            acc += __shfl_xor_sync(0xffffffffu, acc, 1);
            if (half == 0) Ydst[(size_t)(t - 1) * 64 + pair] = acc;
        }
    }

    // ---- tail: y for step LL-1 ----
    __syncthreads();
    {
        const int cbp = (LL - 1) & 15;
        const int hbp = (LL - 1) & 1;
        const float* Cc = &sC[cbp][half * 8][0];
        const float* Hh = &sH[hbp][pY][half * 8];
        float a0 = 0.f, a1 = 0.f;
#pragma unroll
        for (int i = 0; i < 4; i++) {
            a0 = fmaf(Cc[(2 * i    ) * 4 + rY], Hh[2 * i    ], a0);
            a1 = fmaf(Cc[(2 * i + 1) * 4 + rY], Hh[2 * i + 1], a1);
        }
        float acc = a0 + a1;
        acc += __shfl_xor_sync(0xffffffffu, acc, 1);
        if (half == 0) Ydst[(size_t)(LL - 1) * 64 + pair] = acc;
    }
}

// ---------------- combine partials + D_skip + z-gate ------------------------------
__global__ void combine_kernel(const float* __restrict__ D_skip)
{
    const int idx = blockIdx.x * blockDim.x + threadIdx.x; // [0, 8192*1024)
    const int c    = idx & 1023;
    const int row  = idx >> 10;
    const int head = c >> 6;
    const int d    = c & 63;
    const int b    = row >> 11;
    const int t    = row & (LL - 1);
    const int base = (b * 16 + head) * 8;
    float y = 0.f;
#pragma unroll
    for (int nb = 0; nb < 8; nb++)
        y += g_yp[(size_t)(base + nb) * LL * 64 + (size_t)t * 64 + d];
    const float x = g_X[(size_t)row * 1024 + c];
    y += x * D_skip[head];
    const float z = g_zx[(size_t)row * 3088 + c];
    g_g[(size_t)row * 1024 + c] = y * (z / (1.f + expf(-z)));
}

// ---------------- RMSNorm ---------------------------------------------------------
__global__ void __launch_bounds__(256) rms_kernel(float* __restrict__ out)
{
    const int warp = threadIdx.x >> 5;
    const int lane = threadIdx.x & 31;
    const int row  = blockIdx.x * 8 + warp;
    const float* r = g_res + (size_t)row * 512;
    float v[16];
    float ss = 0.f;
#pragma unroll
    for (int i = 0; i < 16; i++) { v[i] = r[lane + i * 32]; ss = fmaf(v[i], v[i], ss); }
#pragma unroll
    for (int o = 16; o >= 1; o >>= 1) ss += __shfl_xor_sync(0xffffffffu, ss, o);
    const float sc = rsqrtf(ss * (1.f / 512.f) + 1e-5f);
    float* o = out + (size_t)row * 512;
#pragma unroll
    for (int i = 0; i < 16; i++) o[lane + i * 32] = v[i] * sc;
}

// ---------------- launch ----------------------------------------------------------
extern "C" void kernel_launch(void* const* d_in, const int* in_sizes, int n_in,
                              void* d_out, int out_size)
{
    const float* hs      = (const float*)d_in[0];
    const float* W_in    = (const float*)d_in[1];
    const float* conv_w  = (const float*)d_in[2];
    const float* conv_b  = (const float*)d_in[3];
    const float* dt_bias = (const float*)d_in[4];
    const float* A_log   = (const float*)d_in[5];
    const float* D_skip  = (const float*)d_in[6];
    const float* W_out   = (const float*)d_in[7];
    float* out = (float*)d_out;

    gemm1_kernel<<<dim3(25, 64), 256>>>(hs, W_in);
    conv_kernel<<<NROWS * 2048 / 256, 256>>>(conv_w, conv_b);
    dt_kernel<<<NROWS * 16 / 256, 256>>>(dt_bias, A_log);
    scan_kernel<<<512, 128>>>();
    combine_kernel<<<NROWS * 1024 / 256, 256>>>(D_skip);
    gemm2_kernel<<<dim3(4, 64), 256>>>(W_out, hs);
    rms_kernel<<<NROWS / 8, 256>>>(out);
}

// round 8
// speedup vs baseline: 1.0787x; 1.0787x over previous
#include <cuda_runtime.h>
#include <math.h>
#include <stdint.h>

#define LL 2048
#define NROWS 8192   // B*L

// ---------------- scratch (device globals; no runtime allocation) ----------------
static __device__ float g_zx [NROWS * 3088]; // zxbcdt
static __device__ float g_X  [NROWS * 1024]; // silu(conv) x part
static __device__ float g_Bm [NROWS * 512];
static __device__ float g_Cm [NROWS * 512];
static __device__ float g_dt [NROWS * 16];
static __device__ float g_dec[NROWS * 16];
static __device__ float g_yp [1024 * LL * 32]; // y partials per (b,h,nb,ph)
static __device__ float g_g  [NROWS * 1024]; // gated
static __device__ float g_res[NROWS * 512];  // pre-norm residual

// ---------------- tf32 helpers ----------------------------------------------------
__device__ __forceinline__ uint32_t f2tf32(float v) {
    uint32_t r;
    asm("cvt.rna.tf32.f32 %0, %1;" : "=r"(r) : "f"(v));
    return r;
}
__device__ __forceinline__ void split_tf32(float v, float& hi, float& lo) {
    uint32_t h = f2tf32(v);
    hi = __uint_as_float(h);
    float l = v - hi;                 // exact in fp32
    lo = __uint_as_float(f2tf32(l));
}
__device__ __forceinline__ void mma_tf32(float d[4],
                                         uint32_t a0, uint32_t a1, uint32_t a2, uint32_t a3,
                                         uint32_t b0, uint32_t b1) {
    asm volatile(
        "mma.sync.aligned.m16n8k8.row.col.f32.tf32.tf32.f32 "
        "{%0,%1,%2,%3}, {%4,%5,%6,%7}, {%8,%9}, {%0,%1,%2,%3};"
        : "+f"(d[0]), "+f"(d[1]), "+f"(d[2]), "+f"(d[3])
        : "r"(a0), "r"(a1), "r"(a2), "r"(a3), "r"(b0), "r"(b1));
}

// ---------------- cp.async helpers -------------------------------------------------
__device__ __forceinline__ void cp16(void* smem, const void* g) {
    uint32_t s = (uint32_t)__cvta_generic_to_shared(smem);
    asm volatile("cp.async.cg.shared.global [%0], [%1], 16;" :: "r"(s), "l"(g) : "memory");
}
__device__ __forceinline__ void cp4(void* smem, const void* g) {
    uint32_t s = (uint32_t)__cvta_generic_to_shared(smem);
    asm volatile("cp.async.ca.shared.global [%0], [%1], 4;" :: "r"(s), "l"(g) : "memory");
}
#define CP_COMMIT() asm volatile("cp.async.commit_group;" ::: "memory")
#define CP_WAIT8()  asm volatile("cp.async.wait_group 8;" ::: "memory")

// ---------------- TF32 tensor-core GEMM: C = A(MxK) @ B(KxN) [+ Res] --------------
template<int Nv, int Kv, bool GUARD, bool ADDRES>
__device__ __forceinline__ void gemm_tf32_body(const float* __restrict__ A,
                                               const float* __restrict__ Bw,
                                               float* __restrict__ C,
                                               const float* __restrict__ Res)
{
    __shared__ __align__(16) float sA[2][2][8][136]; // [buf][hi/lo][k][row]
    __shared__ __align__(16) float sB[2][2][8][136]; // [buf][hi/lo][k][col]

    const int tid   = threadIdx.x;
    const int warp  = tid >> 5;
    const int lane  = tid & 31;
    const int gid   = lane >> 2;   // 0..7
    const int tig   = lane & 3;    // 0..3
    const int warpM = warp & 1;    // 0..1 (64 rows each)
    const int warpN = warp >> 1;   // 0..3 (32 cols each)

    const int aRow = tid >> 1;         // 0..127
    const int aCol = (tid & 1) * 4;    // 0 or 4
    const int bRow = tid >> 5;         // 0..7
    const int bCol = (tid & 31) * 4;   // 0..124

    const int nbase = blockIdx.x * 128;
    const int mbase = blockIdx.y * 128;
    const float* Ap = A + (size_t)(mbase + aRow) * Kv + aCol;
    const float* Bp = Bw + (size_t)bRow * Nv + nbase + bCol;
    const bool  bOK = (!GUARD) || (nbase + bCol + 3 < Nv);

    float acc[4][4][4];
#pragma unroll
    for (int mt = 0; mt < 4; mt++)
#pragma unroll
        for (int nt = 0; nt < 4; nt++)
#pragma unroll
            for (int i = 0; i < 4; i++) acc[mt][nt][i] = 0.f;

    {
        float4 av = *(const float4*)Ap;
        float4 bv = bOK ? *(const float4*)Bp : make_float4(0.f,0.f,0.f,0.f);
        float h, l;
        split_tf32(av.x, h, l); sA[0][0][aCol+0][aRow] = h; sA[0][1][aCol+0][aRow] = l;
        split_tf32(av.y, h, l); sA[0][0][aCol+1][aRow] = h; sA[0][1][aCol+1][aRow] = l;
        split_tf32(av.z, h, l); sA[0][0][aCol+2][aRow] = h; sA[0][1][aCol+2][aRow] = l;
        split_tf32(av.w, h, l); sA[0][0][aCol+3][aRow] = h; sA[0][1][aCol+3][aRow] = l;
        float4 bh, bl;
        split_tf32(bv.x, bh.x, bl.x); split_tf32(bv.y, bh.y, bl.y);
        split_tf32(bv.z, bh.z, bl.z); split_tf32(bv.w, bh.w, bl.w);
        *(float4*)&sB[0][0][bRow][bCol] = bh;
        *(float4*)&sB[0][1][bRow][bCol] = bl;
    }
    __syncthreads();

    const int NK = Kv / 8;
    for (int ks = 0; ks < NK; ks++) {
        const int buf = ks & 1;
        float4 av, bv;
        const bool hasNext = (ks + 1 < NK);
        if (hasNext) {
            av = *(const float4*)(Ap + (ks + 1) * 8);
            bv = bOK ? *(const float4*)(Bp + (size_t)(ks + 1) * 8 * Nv)
                     : make_float4(0.f,0.f,0.f,0.f);
        }

        const float (*Ah)[136] = sA[buf][0];
        const float (*Al)[136] = sA[buf][1];
        const float (*Bh)[136] = sB[buf][0];
        const float (*Bl)[136] = sB[buf][1];

        uint32_t ah[4][4], al[4][4], bh[4][2], bl[4][2];
#pragma unroll
        for (int mt = 0; mt < 4; mt++) {
            const int r = warpM * 64 + mt * 16 + gid;
            ah[mt][0] = __float_as_uint(Ah[tig    ][r    ]);
            ah[mt][1] = __float_as_uint(Ah[tig    ][r + 8]);
            ah[mt][2] = __float_as_uint(Ah[tig + 4][r    ]);
            ah[mt][3] = __float_as_uint(Ah[tig + 4][r + 8]);
            al[mt][0] = __float_as_uint(Al[tig    ][r    ]);
            al[mt][1] = __float_as_uint(Al[tig    ][r + 8]);
            al[mt][2] = __float_as_uint(Al[tig + 4][r    ]);
            al[mt][3] = __float_as_uint(Al[tig + 4][r + 8]);
        }
#pragma unroll
        for (int nt = 0; nt < 4; nt++) {
            const int c = warpN * 32 + nt * 8 + gid;
            bh[nt][0] = __float_as_uint(Bh[tig    ][c]);
            bh[nt][1] = __float_as_uint(Bh[tig + 4][c]);
            bl[nt][0] = __float_as_uint(Bl[tig    ][c]);
            bl[nt][1] = __float_as_uint(Bl[tig + 4][c]);
        }

#pragma unroll
        for (int mt = 0; mt < 4; mt++)
#pragma unroll
            for (int nt = 0; nt < 4; nt++) {
                mma_tf32(acc[mt][nt], ah[mt][0], ah[mt][1], ah[mt][2], ah[mt][3],
                         bh[nt][0], bh[nt][1]);
                mma_tf32(acc[mt][nt], ah[mt][0], ah[mt][1], ah[mt][2], ah[mt][3],
                         bl[nt][0], bl[nt][1]);
                mma_tf32(acc[mt][nt], al[mt][0], al[mt][1], al[mt][2], al[mt][3],
                         bh[nt][0], bh[nt][1]);
            }

        if (hasNext) {
            const int nb = buf ^ 1;
            float h, l;
            split_tf32(av.x, h, l); sA[nb][0][aCol+0][aRow] = h; sA[nb][1][aCol+0][aRow] = l;
            split_tf32(av.y, h, l); sA[nb][0][aCol+1][aRow] = h; sA[nb][1][aCol+1][aRow] = l;
            split_tf32(av.z, h, l); sA[nb][0][aCol+2][aRow] = h; sA[nb][1][aCol+2][aRow] = l;
            split_tf32(av.w, h, l); sA[nb][0][aCol+3][aRow] = h; sA[nb][1][aCol+3][aRow] = l;
            float4 bhh, bll;
            split_tf32(bv.x, bhh.x, bll.x); split_tf32(bv.y, bhh.y, bll.y);
            split_tf32(bv.z, bhh.z, bll.z); split_tf32(bv.w, bhh.w, bll.w);
            *(float4*)&sB[nb][0][bRow][bCol] = bhh;
            *(float4*)&sB[nb][1][bRow][bCol] = bll;
        }
        __syncthreads();
    }

#pragma unroll
    for (int mt = 0; mt < 4; mt++) {
        const int row0 = mbase + warpM * 64 + mt * 16 + gid;
#pragma unroll
        for (int nt = 0; nt < 4; nt++) {
            const int col = nbase + warpN * 32 + nt * 8 + tig * 2;
            if (!GUARD || col < Nv) {
                float2 v0 = make_float2(acc[mt][nt][0], acc[mt][nt][1]);
                float2 v1 = make_float2(acc[mt][nt][2], acc[mt][nt][3]);
                if (ADDRES) {
                    float2 r0 = *(const float2*)(Res + (size_t)row0 * Nv + col);
                    float2 r1 = *(const float2*)(Res + (size_t)(row0 + 8) * Nv + col);
                    v0.x += r0.x; v0.y += r0.y; v1.x += r1.x; v1.y += r1.y;
                }
                *(float2*)(C + (size_t)row0 * Nv + col)       = v0;
                *(float2*)(C + (size_t)(row0 + 8) * Nv + col) = v1;
            }
        }
    }
}

__global__ void __launch_bounds__(256) gemm1_kernel(const float* __restrict__ A,
                                                    const float* __restrict__ W)
{
    gemm_tf32_body<3088, 512, true, false>(A, W, g_zx, nullptr);
}

__global__ void __launch_bounds__(256) gemm2_kernel(const float* __restrict__ W,
                                                    const float* __restrict__ Res)
{
    gemm_tf32_body<512, 1024, false, true>(g_g, W, g_res, Res);
}

// ---------------- conv1d (K=4, causal) + bias + silu + split ----------------------
__global__ void conv_kernel(const float* __restrict__ conv_w,
                            const float* __restrict__ conv_b)
{
    const int idx = blockIdx.x * blockDim.x + threadIdx.x; // [0, 8192*2048)
    const int c   = idx & 2047;
    const int row = idx >> 11;
    const int t   = row & (LL - 1);
    float acc = conv_b[c];
#pragma unroll
    for (int k = 0; k < 4; k++) {
        const int tt = t - 3 + k;
        if (tt >= 0)
            acc = fmaf(g_zx[(size_t)(row - (3 - k)) * 3088 + 1024 + c], conv_w[c * 4 + k], acc);
    }
    const float v = acc / (1.f + expf(-acc)); // silu
    if (c < 1024)       g_X [(size_t)row * 1024 + c]          = v;
    else if (c < 1536)  g_Bm[(size_t)row * 512  + (c - 1024)] = v;
    else                g_Cm[(size_t)row * 512  + (c - 1536)] = v;
}

// ---------------- dt / decay ------------------------------------------------------
__global__ void dt_kernel(const float* __restrict__ dt_bias,
                          const float* __restrict__ A_log)
{
    const int idx = blockIdx.x * blockDim.x + threadIdx.x; // [0, 8192*16)
    const int h   = idx & 15;
    const int row = idx >> 4;
    const float x  = g_zx[(size_t)row * 3088 + 3072 + h] + dt_bias[h];
    const float dt = (x > 20.f) ? x : log1pf(expf(x));
    g_dt [idx] = dt;
    g_dec[idx] = expf(-expf(A_log[h]) * dt);
}

// ---------------- selective scan v4 ------------------------------------------------
// Grid: 1024 CTAs = (b, head, nb of 16 states, ph of 8 p's). 64 threads (2 warps).
// Two timesteps per wait+barrier. 16-buffer cp.async ring, prefetch distance 10,
// wait_group 8 (retires the next loop's two step-groups before the barrier).
// Update: n_l = tid&15, pq = tid>>4 owns (p0,p1) = local p pair.
// y: pair = tid>>1 -> (rY = pair>>3, pY = pair&7); 2 threads per output (8+8 states).
// Buffer safety: buffer (t+10)&15 was last read at step t-6 (3 loop iters, >=3
// barriers earlier). sH double-phase [(t>>1)&1][step j]: writers of a phase are
// separated from its readers by the barrier in between; opposite-phase writes
// never collide with in-flight readers.
__global__ void __launch_bounds__(64) scan_kernel()
{
    const int bx = blockIdx.x;
    const int ph = bx & 1;
    const int nb = (bx >> 1) & 7;
    const int hh = (bx >> 4) & 15;
    const int bb = bx >> 8;
    const int tid  = threadIdx.x;
    const int n_l  = tid & 15;
    const int pq   = tid >> 4;      // 0..3
    const int pair = tid >> 1;      // 0..31
    const int half = tid & 1;
    const int rY   = pair >> 3;     // 0..3
    const int pY   = pair & 7;      // 0..7

    __shared__ __align__(16) float sB[16][16][4];
    __shared__ __align__(16) float sC[16][16][4];
    __shared__ __align__(16) float sX[16][4][8];
    __shared__ __align__(16) float sS[16][2];
    __shared__ __align__(16) float sH[2][2][16][9];  // [phase][stepj][n][p(8)+pad]

    const float* Bsrc = g_Bm  + (size_t)bb * LL * 512  + nb * 64;
    const float* Csrc = g_Cm  + (size_t)bb * LL * 512  + nb * 64;
    const float* Xsrc = g_X   + (size_t)bb * LL * 1024 + hh * 64 + ph * 8;
    const float* Dsrc = g_dec + (size_t)bb * LL * 16   + hh;
    const float* Tsrc = g_dt  + (size_t)bb * LL * 16   + hh;
    float* Ydst = g_yp + (size_t)bx * LL * 32;

    // loader routing: tid 0-15 B, 16-31 C, 32-39 X (r=j>>1, half-row j&1), 40 dec, 41 dt
    const int li = tid & 15;
    const int xr = (tid - 32) >> 1;
    const int xh = (tid - 32) & 1;

    // prologue: issue steps 0..9 (10 groups); then make steps 0,1 visible.
#pragma unroll
    for (int s = 0; s < 10; s++) {
        if (tid < 16)       cp16(&sB[s][li][0], Bsrc + (size_t)s * 512 + li * 4);
        else if (tid < 32)  cp16(&sC[s][li][0], Csrc + (size_t)s * 512 + li * 4);
        else if (tid < 40)  cp16(&sX[s][xr][xh * 4], Xsrc + (size_t)s * 1024 + xr * 16 + xh * 4);
        else if (tid == 40) cp4(&sS[s][0], Dsrc + (size_t)s * 16);
        else if (tid == 41) cp4(&sS[s][1], Tsrc + (size_t)s * 16);
        CP_COMMIT();
    }
    CP_WAIT8();       // retires groups 0,1
    __syncthreads();

    float h0 = 0.f, h1 = 0.f;
    const int p0 = pq * 2;
    const int p1 = p0 + 1;

    for (int t = 0; t < LL; t += 2) {
        const int phase = (t >> 1) & 1;

        // ---- updates for steps t, t+1 (buffers visible from previous wait+sync) ----
#pragma unroll
        for (int j = 0; j < 2; j++) {
            const int cb = (t + j) & 15;
            const float4 Bv  = *(const float4*)&sB[cb][n_l][0];
            const float  dec = sS[cb][0];
            const float  dtv = sS[cb][1];
            const float u0 = (Bv.x * sX[cb][0][p0] + Bv.y * sX[cb][1][p0])
                           + (Bv.z * sX[cb][2][p0] + Bv.w * sX[cb][3][p0]);
            const float u1 = (Bv.x * sX[cb][0][p1] + Bv.y * sX[cb][1][p1])
                           + (Bv.z * sX[cb][2][p1] + Bv.w * sX[cb][3][p1]);
            h0 = fmaf(dec, h0, dtv * u0);
            h1 = fmaf(dec, h1, dtv * u1);
            sH[phase][j][n_l][p0] = h0;
            sH[phase][j][n_l][p1] = h1;
        }

        // ---- prefetch steps t+10, t+11 (always commit to keep FIFO arithmetic) ----
#pragma unroll
        for (int j = 0; j < 2; j++) {
            const int ts = t + 10 + j;
            if (ts < LL) {
                const int sb = ts & 15;
                if (tid < 16)       cp16(&sB[sb][li][0], Bsrc + (size_t)ts * 512 + li * 4);
                else if (tid < 32)  cp16(&sC[sb][li][0], Csrc + (size_t)ts * 512 + li * 4);
                else if (tid < 40)  cp16(&sX[sb][xr][xh * 4], Xsrc + (size_t)ts * 1024 + xr * 16 + xh * 4);
                else if (tid == 40) cp4(&sS[sb][0], Dsrc + (size_t)ts * 16);
                else if (tid == 41) cp4(&sS[sb][1], Tsrc + (size_t)ts * 16);
            }
            CP_COMMIT();
        }

        // ---- retire groups t+2, t+3; publish sH ----
        CP_WAIT8();
        __syncthreads();

        // ---- y partials for steps t, t+1 ----
#pragma unroll
        for (int j = 0; j < 2; j++) {
            const int cb = (t + j) & 15;
            float a0 = 0.f, a1 = 0.f;
#pragma unroll
            for (int i = 0; i < 4; i++) {
                a0 = fmaf(sC[cb][half * 8 + 2 * i    ][rY], sH[phase][j][half * 8 + 2 * i    ][pY], a0);
                a1 = fmaf(sC[cb][half * 8 + 2 * i + 1][rY], sH[phase][j][half * 8 + 2 * i + 1][pY], a1);
            }
            float acc = a0 + a1;
            acc += __shfl_xor_sync(0xffffffffu, acc, 1);
            if (half == 0) Ydst[(size_t)(t + j) * 32 + pair] = acc;
        }
    }
}

// ---------------- combine partials + D_skip + z-gate ------------------------------
__global__ void combine_kernel(const float* __restrict__ D_skip)
{
    const int idx = blockIdx.x * blockDim.x + threadIdx.x; // [0, 8192*1024)
    const int c    = idx & 1023;
    const int row  = idx >> 10;
    const int head = c >> 6;
    const int c6   = c & 63;
    const int r    = c6 >> 4;
    const int p    = c6 & 15;
    const int ph   = p >> 3;
    const int pl   = p & 7;
    const int b    = row >> 11;
    const int t    = row & (LL - 1);
    const int pairidx = r * 8 + pl;
    const int bx0 = (b * 16 + head) * 16 + ph;   // nb=0 CTA index; nb stride = 2
    float y = 0.f;
#pragma unroll
    for (int nb = 0; nb < 8; nb++)
        y += g_yp[(size_t)(bx0 + nb * 2) * (LL * 32) + (size_t)t * 32 + pairidx];
    const float x = g_X[(size_t)row * 1024 + c];
    y += x * D_skip[head];
    const float z = g_zx[(size_t)row * 3088 + c];
    g_g[(size_t)row * 1024 + c] = y * (z / (1.f + expf(-z)));
}

// ---------------- RMSNorm ---------------------------------------------------------
__global__ void __launch_bounds__(256) rms_kernel(float* __restrict__ out)
{
    const int warp = threadIdx.x >> 5;
    const int lane = threadIdx.x & 31;
    const int row  = blockIdx.x * 8 + warp;
    const float* r = g_res + (size_t)row * 512;
    float v[16];
    float ss = 0.f;
#pragma unroll
    for (int i = 0; i < 16; i++) { v[i] = r[lane + i * 32]; ss = fmaf(v[i], v[i], ss); }
#pragma unroll
    for (int o = 16; o >= 1; o >>= 1) ss += __shfl_xor_sync(0xffffffffu, ss, o);
    const float sc = rsqrtf(ss * (1.f / 512.f) + 1e-5f);
    float* o = out + (size_t)row * 512;
#pragma unroll
    for (int i = 0; i < 16; i++) o[lane + i * 32] = v[i] * sc;
}

// ---------------- launch ----------------------------------------------------------
extern "C" void kernel_launch(void* const* d_in, const int* in_sizes, int n_in,
                              void* d_out, int out_size)
{
    const float* hs      = (const float*)d_in[0];
    const float* W_in    = (const float*)d_in[1];
    const float* conv_w  = (const float*)d_in[2];
    const float* conv_b  = (const float*)d_in[3];
    const float* dt_bias = (const float*)d_in[4];
    const float* A_log   = (const float*)d_in[5];
    const float* D_skip  = (const float*)d_in[6];
    const float* W_out   = (const float*)d_in[7];
    float* out = (float*)d_out;

    gemm1_kernel<<<dim3(25, 64), 256>>>(hs, W_in);
    conv_kernel<<<NROWS * 2048 / 256, 256>>>(conv_w, conv_b);
    dt_kernel<<<NROWS * 16 / 256, 256>>>(dt_bias, A_log);
    scan_kernel<<<1024, 64>>>();
    combine_kernel<<<NROWS * 1024 / 256, 256>>>(D_skip);
    gemm2_kernel<<<dim3(4, 64), 256>>>(W_out, hs);
    rms_kernel<<<NROWS / 8, 256>>>(out);
}

// round 9
// speedup vs baseline: 1.1445x; 1.0610x over previous
#include <cuda_runtime.h>
#include <math.h>
#include <stdint.h>

#define LL 2048
#define NROWS 8192   // B*L

// ---------------- scratch (device globals; no runtime allocation) ----------------
static __device__ float g_zx [NROWS * 3088]; // zxbcdt
static __device__ float g_X  [NROWS * 1024]; // silu(conv) x part
static __device__ float g_Bm [NROWS * 512];  // B  [row][n*4+r]
static __device__ float g_CmT[NROWS * 512];  // C^T [row][r*128+n]
static __device__ float g_ddt[NROWS * 16 * 2]; // packed (dec, dt) per (row, head)
static __device__ float g_yp [2048 * LL * 16]; // y partials per (b,h,nb8,pp4)
static __device__ float g_g  [NROWS * 1024]; // gated
static __device__ float g_res[NROWS * 512];  // pre-norm residual

// ---------------- tf32 helpers ----------------------------------------------------
__device__ __forceinline__ uint32_t f2tf32(float v) {
    uint32_t r;
    asm("cvt.rna.tf32.f32 %0, %1;" : "=r"(r) : "f"(v));
    return r;
}
__device__ __forceinline__ void split_tf32(float v, float& hi, float& lo) {
    uint32_t h = f2tf32(v);
    hi = __uint_as_float(h);
    float l = v - hi;                 // exact in fp32
    lo = __uint_as_float(f2tf32(l));
}
__device__ __forceinline__ void mma_tf32(float d[4],
                                         uint32_t a0, uint32_t a1, uint32_t a2, uint32_t a3,
                                         uint32_t b0, uint32_t b1) {
    asm volatile(
        "mma.sync.aligned.m16n8k8.row.col.f32.tf32.tf32.f32 "
        "{%0,%1,%2,%3}, {%4,%5,%6,%7}, {%8,%9}, {%0,%1,%2,%3};"
        : "+f"(d[0]), "+f"(d[1]), "+f"(d[2]), "+f"(d[3])
        : "r"(a0), "r"(a1), "r"(a2), "r"(a3), "r"(b0), "r"(b1));
}

// ---------------- cp.async helpers -------------------------------------------------
__device__ __forceinline__ void cp16(void* smem, const void* g) {
    uint32_t s = (uint32_t)__cvta_generic_to_shared(smem);
    asm volatile("cp.async.cg.shared.global [%0], [%1], 16;" :: "r"(s), "l"(g) : "memory");
}
__device__ __forceinline__ void cp8(void* smem, const void* g) {
    uint32_t s = (uint32_t)__cvta_generic_to_shared(smem);
    asm volatile("cp.async.ca.shared.global [%0], [%1], 8;" :: "r"(s), "l"(g) : "memory");
}
#define CP_COMMIT() asm volatile("cp.async.commit_group;" ::: "memory")
#define CP_WAIT9()  asm volatile("cp.async.wait_group 9;" ::: "memory")

// ---------------- TF32 tensor-core GEMM: C = A(MxK) @ B(KxN) [+ Res] --------------
template<int Nv, int Kv, bool GUARD, bool ADDRES>
__device__ __forceinline__ void gemm_tf32_body(const float* __restrict__ A,
                                               const float* __restrict__ Bw,
                                               float* __restrict__ C,
                                               const float* __restrict__ Res)
{
    __shared__ __align__(16) float sA[2][2][8][136]; // [buf][hi/lo][k][row]
    __shared__ __align__(16) float sB[2][2][8][136]; // [buf][hi/lo][k][col]

    const int tid   = threadIdx.x;
    const int warp  = tid >> 5;
    const int lane  = tid & 31;
    const int gid   = lane >> 2;   // 0..7
    const int tig   = lane & 3;    // 0..3
    const int warpM = warp & 1;    // 0..1 (64 rows each)
    const int warpN = warp >> 1;   // 0..3 (32 cols each)

    const int aRow = tid >> 1;         // 0..127
    const int aCol = (tid & 1) * 4;    // 0 or 4
    const int bRow = tid >> 5;         // 0..7
    const int bCol = (tid & 31) * 4;   // 0..124

    const int nbase = blockIdx.x * 128;
    const int mbase = blockIdx.y * 128;
    const float* Ap = A + (size_t)(mbase + aRow) * Kv + aCol;
    const float* Bp = Bw + (size_t)bRow * Nv + nbase + bCol;
    const bool  bOK = (!GUARD) || (nbase + bCol + 3 < Nv);

    float acc[4][4][4];
#pragma unroll
    for (int mt = 0; mt < 4; mt++)
#pragma unroll
        for (int nt = 0; nt < 4; nt++)
#pragma unroll
            for (int i = 0; i < 4; i++) acc[mt][nt][i] = 0.f;

    {
        float4 av = *(const float4*)Ap;
        float4 bv = bOK ? *(const float4*)Bp : make_float4(0.f,0.f,0.f,0.f);
        float h, l;
        split_tf32(av.x, h, l); sA[0][0][aCol+0][aRow] = h; sA[0][1][aCol+0][aRow] = l;
        split_tf32(av.y, h, l); sA[0][0][aCol+1][aRow] = h; sA[0][1][aCol+1][aRow] = l;
        split_tf32(av.z, h, l); sA[0][0][aCol+2][aRow] = h; sA[0][1][aCol+2][aRow] = l;
        split_tf32(av.w, h, l); sA[0][0][aCol+3][aRow] = h; sA[0][1][aCol+3][aRow] = l;
        float4 bh, bl;
        split_tf32(bv.x, bh.x, bl.x); split_tf32(bv.y, bh.y, bl.y);
        split_tf32(bv.z, bh.z, bl.z); split_tf32(bv.w, bh.w, bl.w);
        *(float4*)&sB[0][0][bRow][bCol] = bh;
        *(float4*)&sB[0][1][bRow][bCol] = bl;
    }
    __syncthreads();

    const int NK = Kv / 8;
    for (int ks = 0; ks < NK; ks++) {
        const int buf = ks & 1;
        float4 av, bv;
        const bool hasNext = (ks + 1 < NK);
        if (hasNext) {
            av = *(const float4*)(Ap + (ks + 1) * 8);
            bv = bOK ? *(const float4*)(Bp + (size_t)(ks + 1) * 8 * Nv)
                     : make_float4(0.f,0.f,0.f,0.f);
        }

        const float (*Ah)[136] = sA[buf][0];
        const float (*Al)[136] = sA[buf][1];
        const float (*Bh)[136] = sB[buf][0];
        const float (*Bl)[136] = sB[buf][1];

        uint32_t ah[4][4], al[4][4], bh[4][2], bl[4][2];
#pragma unroll
        for (int mt = 0; mt < 4; mt++) {
            const int r = warpM * 64 + mt * 16 + gid;
            ah[mt][0] = __float_as_uint(Ah[tig    ][r    ]);
            ah[mt][1] = __float_as_uint(Ah[tig    ][r + 8]);
            ah[mt][2] = __float_as_uint(Ah[tig + 4][r    ]);
            ah[mt][3] = __float_as_uint(Ah[tig + 4][r + 8]);
            al[mt][0] = __float_as_uint(Al[tig    ][r    ]);
            al[mt][1] = __float_as_uint(Al[tig    ][r + 8]);
            al[mt][2] = __float_as_uint(Al[tig + 4][r    ]);
            al[mt][3] = __float_as_uint(Al[tig + 4][r + 8]);
        }
#pragma unroll
        for (int nt = 0; nt < 4; nt++) {
            const int c = warpN * 32 + nt * 8 + gid;
            bh[nt][0] = __float_as_uint(Bh[tig    ][c]);
            bh[nt][1] = __float_as_uint(Bh[tig + 4][c]);
            bl[nt][0] = __float_as_uint(Bl[tig    ][c]);
            bl[nt][1] = __float_as_uint(Bl[tig + 4][c]);
        }

#pragma unroll
        for (int mt = 0; mt < 4; mt++)
#pragma unroll
            for (int nt = 0; nt < 4; nt++) {
                mma_tf32(acc[mt][nt], ah[mt][0], ah[mt][1], ah[mt][2], ah[mt][3],
                         bh[nt][0], bh[nt][1]);
                mma_tf32(acc[mt][nt], ah[mt][0], ah[mt][1], ah[mt][2], ah[mt][3],
                         bl[nt][0], bl[nt][1]);
                mma_tf32(acc[mt][nt], al[mt][0], al[mt][1], al[mt][2], al[mt][3],
                         bh[nt][0], bh[nt][1]);
            }

        if (hasNext) {
            const int nb = buf ^ 1;
            float h, l;
            split_tf32(av.x, h, l); sA[nb][0][aCol+0][aRow] = h; sA[nb][1][aCol+0][aRow] = l;
            split_tf32(av.y, h, l); sA[nb][0][aCol+1][aRow] = h; sA[nb][1][aCol+1][aRow] = l;
            split_tf32(av.z, h, l); sA[nb][0][aCol+2][aRow] = h; sA[nb][1][aCol+2][aRow] = l;
            split_tf32(av.w, h, l); sA[nb][0][aCol+3][aRow] = h; sA[nb][1][aCol+3][aRow] = l;
            float4 bhh, bll;
            split_tf32(bv.x, bhh.x, bll.x); split_tf32(bv.y, bhh.y, bll.y);
            split_tf32(bv.z, bhh.z, bll.z); split_tf32(bv.w, bhh.w, bll.w);
            *(float4*)&sB[nb][0][bRow][bCol] = bhh;
            *(float4*)&sB[nb][1][bRow][bCol] = bll;
        }
        __syncthreads();
    }

#pragma unroll
    for (int mt = 0; mt < 4; mt++) {
        const int row0 = mbase + warpM * 64 + mt * 16 + gid;
#pragma unroll
        for (int nt = 0; nt < 4; nt++) {
            const int col = nbase + warpN * 32 + nt * 8 + tig * 2;
            if (!GUARD || col < Nv) {
                float2 v0 = make_float2(acc[mt][nt][0], acc[mt][nt][1]);
                float2 v1 = make_float2(acc[mt][nt][2], acc[mt][nt][3]);
                if (ADDRES) {
                    float2 r0 = *(const float2*)(Res + (size_t)row0 * Nv + col);
                    float2 r1 = *(const float2*)(Res + (size_t)(row0 + 8) * Nv + col);
                    v0.x += r0.x; v0.y += r0.y; v1.x += r1.x; v1.y += r1.y;
                }
                *(float2*)(C + (size_t)row0 * Nv + col)       = v0;
                *(float2*)(C + (size_t)(row0 + 8) * Nv + col) = v1;
            }
        }
    }
}

__global__ void __launch_bounds__(256) gemm1_kernel(const float* __restrict__ A,
                                                    const float* __restrict__ W)
{
    gemm_tf32_body<3088, 512, true, false>(A, W, g_zx, nullptr);
}

__global__ void __launch_bounds__(256) gemm2_kernel(const float* __restrict__ W,
                                                    const float* __restrict__ Res)
{
    gemm_tf32_body<512, 1024, false, true>(g_g, W, g_res, Res);
}

// ---------------- conv1d (K=4, causal) + bias + silu + split ----------------------
// C part additionally stored transposed: g_CmT[row][r*128+n]
__global__ void conv_kernel(const float* __restrict__ conv_w,
                            const float* __restrict__ conv_b)
{
    const int idx = blockIdx.x * blockDim.x + threadIdx.x; // [0, 8192*2048)
    const int c   = idx & 2047;
    const int row = idx >> 11;
    const int t   = row & (LL - 1);
    float acc = conv_b[c];
#pragma unroll
    for (int k = 0; k < 4; k++) {
        const int tt = t - 3 + k;
        if (tt >= 0)
            acc = fmaf(g_zx[(size_t)(row - (3 - k)) * 3088 + 1024 + c], conv_w[c * 4 + k], acc);
    }
    const float v = acc / (1.f + expf(-acc)); // silu
    if (c < 1024)       g_X [(size_t)row * 1024 + c] = v;
    else if (c < 1536)  g_Bm[(size_t)row * 512 + (c - 1024)] = v;
    else {
        const int i = c - 1536;         // n*4 + r
        const int n = i >> 2;
        const int r = i & 3;
        g_CmT[(size_t)row * 512 + r * 128 + n] = v;
    }
}

// ---------------- dt / decay (packed pairs) ---------------------------------------
__global__ void dt_kernel(const float* __restrict__ dt_bias,
                          const float* __restrict__ A_log)
{
    const int idx = blockIdx.x * blockDim.x + threadIdx.x; // [0, 8192*16)
    const int h   = idx & 15;
    const int row = idx >> 4;
    const float x  = g_zx[(size_t)row * 3088 + 3072 + h] + dt_bias[h];
    const float dt = (x > 20.f) ? x : log1pf(expf(x));
    g_ddt[(size_t)idx * 2]     = expf(-expf(A_log[h]) * dt);  // dec
    g_ddt[(size_t)idx * 2 + 1] = dt;
}

// ---------------- selective scan v5 ------------------------------------------------
// Grid: 2048 CTAs = (b4, h16, nb8 of 16 states, pp4 of 4 p's). 32 threads = 1 warp.
// No block barriers: all sync via __syncwarp. cp.async 16-buffer ring, distance 10,
// wait_group 9 (retire exactly one step-group per iteration).
// Update: lane -> n_l = lane&15, pu = lane>>4; owns h[n_l][p_loc = pu*2, pu*2+1].
// X reads are warp-broadcast (all n-lanes share the CTA's p-block).
// y: pair = lane>>1 -> (rY = pair>>2, pY = pair&3); half = lane&1 sums 8 states via
// vector LDS.128 from transposed C (sCT[r][n]) and sH[p][n]; shfl-pair reduce.
__global__ void __launch_bounds__(32) scan_kernel()
{
    const int bx = blockIdx.x;
    const int pp = bx & 3;
    const int nb = (bx >> 2) & 7;
    const int hh = (bx >> 5) & 15;
    const int bb = bx >> 9;
    const int lane = threadIdx.x;
    const int n_l  = lane & 15;
    const int pu   = lane >> 4;     // 0..1
    const int pair = lane >> 1;     // 0..15
    const int half = lane & 1;
    const int rY   = pair >> 2;     // 0..3
    const int pY   = pair & 3;      // 0..3

    __shared__ __align__(16) float sB [16][16][4];  // [buf][n][r]
    __shared__ __align__(16) float sCT[16][4][16];  // [buf][r][n]
    __shared__ __align__(16) float sX [16][4][4];   // [buf][r][p_loc]
    __shared__ __align__(16) float sS [16][2];      // [buf][dec,dt]
    __shared__ __align__(16) float sH [2][4][16];   // [phase][p_loc][n]

    const float* Bsrc = g_Bm  + (size_t)bb * LL * 512  + nb * 64;
    const float* Csrc = g_CmT + (size_t)bb * LL * 512  + nb * 16;
    const float* Xsrc = g_X   + (size_t)bb * LL * 1024 + hh * 64 + pp * 4;
    const float* Ssrc = g_ddt + ((size_t)bb * LL * 16 + hh) * 2;  // +t*32
    float* Ydst = g_yp + (size_t)bx * LL * 16;

    const int li  = lane & 15;
    const int cr  = li >> 2;        // for CT loads (lanes 16..31)
    const int cq  = li & 3;

    // prologue: issue steps 0..9, one commit group each
#pragma unroll
    for (int s = 0; s < 10; s++) {
        if (lane < 16) cp16(&sB[s][li][0], Bsrc + (size_t)s * 512 + li * 4);
        else           cp16(&sCT[s][cr][cq * 4], Csrc + (size_t)s * 512 + cr * 128 + cq * 4);
        if (lane < 4)       cp16(&sX[s][lane][0], Xsrc + (size_t)s * 1024 + lane * 16);
        else if (lane == 4) cp8(&sS[s][0], Ssrc + (size_t)s * 32);
        CP_COMMIT();
    }

    float h0 = 0.f, h1 = 0.f;
    const int p0 = pu * 2;
    const int p1 = p0 + 1;

    for (int t = 0; t < LL; t++) {
        const int cb = t & 15;
        const int hb = t & 1;

        CP_WAIT9();          // retire step t's group (per-thread)
        __syncwarp();        // make all lanes' copies visible

        // ---- state update ----
        const float4 Bv = *(const float4*)&sB[cb][n_l][0];
        const float2 dd = *(const float2*)&sS[cb][0];
        const float2 x0 = *(const float2*)&sX[cb][0][p0];
        const float2 x1 = *(const float2*)&sX[cb][1][p0];
        const float2 x2 = *(const float2*)&sX[cb][2][p0];
        const float2 x3 = *(const float2*)&sX[cb][3][p0];
        const float u0 = (Bv.x * x0.x + Bv.y * x1.x) + (Bv.z * x2.x + Bv.w * x3.x);
        const float u1 = (Bv.x * x0.y + Bv.y * x1.y) + (Bv.z * x2.y + Bv.w * x3.y);
        h0 = fmaf(dd.x, h0, dd.y * u0);
        h1 = fmaf(dd.x, h1, dd.y * u1);
        sH[hb][p0][n_l] = h0;
        sH[hb][p1][n_l] = h1;

        // ---- prefetch step t+10 ----
        const int ts = t + 10;
        if (ts < LL) {
            const int sb = ts & 15;
            if (lane < 16) cp16(&sB[sb][li][0], Bsrc + (size_t)ts * 512 + li * 4);
            else           cp16(&sCT[sb][cr][cq * 4], Csrc + (size_t)ts * 512 + cr * 128 + cq * 4);
            if (lane < 4)       cp16(&sX[sb][lane][0], Xsrc + (size_t)ts * 1024 + lane * 16);
            else if (lane == 4) cp8(&sS[sb][0], Ssrc + (size_t)ts * 32);
        }
        CP_COMMIT();         // unconditional: keeps per-thread FIFO depth fixed

        __syncwarp();        // publish sH to y lanes

        // ---- y partial: y(rY, pY) over this CTA's 16 states ----
        const float4 c0 = *(const float4*)&sCT[cb][rY][half * 8];
        const float4 c1 = *(const float4*)&sCT[cb][rY][half * 8 + 4];
        const float4 hv0 = *(const float4*)&sH[hb][pY][half * 8];
        const float4 hv1 = *(const float4*)&sH[hb][pY][half * 8 + 4];
        float acc = (c0.x * hv0.x + c0.y * hv0.y) + (c0.z * hv0.z + c0.w * hv0.w)
                  + (c1.x * hv1.x + c1.y * hv1.y) + (c1.z * hv1.z + c1.w * hv1.w);
        acc += __shfl_xor_sync(0xffffffffu, acc, 1);
        if (half == 0) Ydst[(size_t)t * 16 + pair] = acc;
    }
}

// ---------------- combine partials + D_skip + z-gate ------------------------------
__global__ void combine_kernel(const float* __restrict__ D_skip)
{
    const int idx = blockIdx.x * blockDim.x + threadIdx.x; // [0, 8192*1024)
    const int c    = idx & 1023;
    const int row  = idx >> 10;
    const int head = c >> 6;
    const int rp   = c & 63;
    const int r    = rp >> 4;
    const int p    = rp & 15;
    const int pp   = p >> 2;
    const int pairidx = r * 4 + (p & 3);
    const int b    = row >> 11;
    const int t    = row & (LL - 1);
    const int bx0  = (b * 16 + head) * 32 + pp;  // nb stride = 4
    float y = 0.f;
#pragma unroll
    for (int nb = 0; nb < 8; nb++)
        y += g_yp[(size_t)(bx0 + nb * 4) * (LL * 16) + (size_t)t * 16 + pairidx];
    const float x = g_X[(size_t)row * 1024 + c];
    y += x * D_skip[head];
    const float z = g_zx[(size_t)row * 3088 + c];
    g_g[(size_t)row * 1024 + c] = y * (z / (1.f + expf(-z)));
}

// ---------------- RMSNorm ---------------------------------------------------------
__global__ void __launch_bounds__(256) rms_kernel(float* __restrict__ out)
{
    const int warp = threadIdx.x >> 5;
    const int lane = threadIdx.x & 31;
    const int row  = blockIdx.x * 8 + warp;
    const float* r = g_res + (size_t)row * 512;
    float v[16];
    float ss = 0.f;
#pragma unroll
    for (int i = 0; i < 16; i++) { v[i] = r[lane + i * 32]; ss = fmaf(v[i], v[i], ss); }
#pragma unroll
    for (int o = 16; o >= 1; o >>= 1) ss += __shfl_xor_sync(0xffffffffu, ss, o);
    const float sc = rsqrtf(ss * (1.f / 512.f) + 1e-5f);
    float* o = out + (size_t)row * 512;
#pragma unroll
    for (int i = 0; i < 16; i++) o[lane + i * 32] = v[i] * sc;
}

// ---------------- launch ----------------------------------------------------------
extern "C" void kernel_launch(void* const* d_in, const int* in_sizes, int n_in,
                              void* d_out, int out_size)
{
    const float* hs      = (const float*)d_in[0];
    const float* W_in    = (const float*)d_in[1];
    const float* conv_w  = (const float*)d_in[2];
    const float* conv_b  = (const float*)d_in[3];
    const float* dt_bias = (const float*)d_in[4];
    const float* A_log   = (const float*)d_in[5];
    const float* D_skip  = (const float*)d_in[6];
    const float* W_out   = (const float*)d_in[7];
    float* out = (float*)d_out;

    gemm1_kernel<<<dim3(25, 64), 256>>>(hs, W_in);
    conv_kernel<<<NROWS * 2048 / 256, 256>>>(conv_w, conv_b);
    dt_kernel<<<NROWS * 16 / 256, 256>>>(dt_bias, A_log);
    scan_kernel<<<2048, 32>>>();
    combine_kernel<<<NROWS * 1024 / 256, 256>>>(D_skip);
    gemm2_kernel<<<dim3(4, 64), 256>>>(W_out, hs);
    rms_kernel<<<NROWS / 8, 256>>>(out);
}

// round 10
// speedup vs baseline: 1.5328x; 1.3393x over previous
#include <cuda_runtime.h>
#include <math.h>
#include <stdint.h>

#define LL 2048
#define NROWS 8192   // B*L
#define QC 64        // chunk length
#define NCHUNK 32    // chunks per batch

// ---------------- scratch (device globals; no runtime allocation) ----------------
static __device__ float g_zx [NROWS * 3088]; // zxbcdt
static __device__ float g_X  [NROWS * 1024]; // silu(conv) x part [row][h*64+r*16+p]
static __device__ float g_BmT[NROWS * 512];  // B^T [row][r*128+n]
static __device__ float g_CmT[NROWS * 512];  // C^T [row][r*128+n]
static __device__ float g_dth[4 * 16 * LL];  // dt  [b,h,t]
static __device__ float g_La [4 * 16 * LL];  // chunk-local cumsum(logdec) [b,h,t]
static __device__ float g_G  [128 * 65536];  // scores [b*32+c][tq*256+sq]
static __device__ float g_P  [2048 * 2048];  // chunk state contrib [(b*32+c)*16+h][n*16+p]
static __device__ float g_S  [2048 * 2048];  // chunk-start states, same layout
static __device__ float g_g  [NROWS * 1024]; // gated
static __device__ float g_res[NROWS * 512];  // pre-norm residual

// ---------------- tf32 helpers ----------------------------------------------------
__device__ __forceinline__ uint32_t f2tf32(float v) {
    uint32_t r;
    asm("cvt.rna.tf32.f32 %0, %1;" : "=r"(r) : "f"(v));
    return r;
}
__device__ __forceinline__ void split_tf32(float v, float& hi, float& lo) {
    uint32_t h = f2tf32(v);
    hi = __uint_as_float(h);
    float l = v - hi;                 // exact in fp32
    lo = __uint_as_float(f2tf32(l));
}
__device__ __forceinline__ void mma_tf32(float d[4],
                                         uint32_t a0, uint32_t a1, uint32_t a2, uint32_t a3,
                                         uint32_t b0, uint32_t b1) {
    asm volatile(
        "mma.sync.aligned.m16n8k8.row.col.f32.tf32.tf32.f32 "
        "{%0,%1,%2,%3}, {%4,%5,%6,%7}, {%8,%9}, {%0,%1,%2,%3};"
        : "+f"(d[0]), "+f"(d[1]), "+f"(d[2]), "+f"(d[3])
        : "r"(a0), "r"(a1), "r"(a2), "r"(a3), "r"(b0), "r"(b1));
}

// ---------------- TF32 tensor-core GEMM: C = A(MxK) @ B(KxN) [+ Res] --------------
template<int Nv, int Kv, bool GUARD, bool ADDRES>
__device__ __forceinline__ void gemm_tf32_body(const float* __restrict__ A,
                                               const float* __restrict__ Bw,
                                               float* __restrict__ C,
                                               const float* __restrict__ Res)
{
    __shared__ __align__(16) float sA[2][2][8][136]; // [buf][hi/lo][k][row]
    __shared__ __align__(16) float sB[2][2][8][136]; // [buf][hi/lo][k][col]

    const int tid   = threadIdx.x;
    const int warp  = tid >> 5;
    const int lane  = tid & 31;
    const int gid   = lane >> 2;
    const int tig   = lane & 3;
    const int warpM = warp & 1;
    const int warpN = warp >> 1;

    const int aRow = tid >> 1;
    const int aCol = (tid & 1) * 4;
    const int bRow = tid >> 5;
    const int bCol = (tid & 31) * 4;

    const int nbase = blockIdx.x * 128;
    const int mbase = blockIdx.y * 128;
    const float* Ap = A + (size_t)(mbase + aRow) * Kv + aCol;
    const float* Bp = Bw + (size_t)bRow * Nv + nbase + bCol;
    const bool  bOK = (!GUARD) || (nbase + bCol + 3 < Nv);

    float acc[4][4][4];
#pragma unroll
    for (int mt = 0; mt < 4; mt++)
#pragma unroll
        for (int nt = 0; nt < 4; nt++)
#pragma unroll
            for (int i = 0; i < 4; i++) acc[mt][nt][i] = 0.f;

    {
        float4 av = *(const float4*)Ap;
        float4 bv = bOK ? *(const float4*)Bp : make_float4(0.f,0.f,0.f,0.f);
        float h, l;
        split_tf32(av.x, h, l); sA[0][0][aCol+0][aRow] = h; sA[0][1][aCol+0][aRow] = l;
        split_tf32(av.y, h, l); sA[0][0][aCol+1][aRow] = h; sA[0][1][aCol+1][aRow] = l;
        split_tf32(av.z, h, l); sA[0][0][aCol+2][aRow] = h; sA[0][1][aCol+2][aRow] = l;
        split_tf32(av.w, h, l); sA[0][0][aCol+3][aRow] = h; sA[0][1][aCol+3][aRow] = l;
        float4 bh, bl;
        split_tf32(bv.x, bh.x, bl.x); split_tf32(bv.y, bh.y, bl.y);
        split_tf32(bv.z, bh.z, bl.z); split_tf32(bv.w, bh.w, bl.w);
        *(float4*)&sB[0][0][bRow][bCol] = bh;
        *(float4*)&sB[0][1][bRow][bCol] = bl;
    }
    __syncthreads();

    const int NK = Kv / 8;
    for (int ks = 0; ks < NK; ks++) {
        const int buf = ks & 1;
        float4 av, bv;
        const bool hasNext = (ks + 1 < NK);
        if (hasNext) {
            av = *(const float4*)(Ap + (ks + 1) * 8);
            bv = bOK ? *(const float4*)(Bp + (size_t)(ks + 1) * 8 * Nv)
                     : make_float4(0.f,0.f,0.f,0.f);
        }

        const float (*Ah)[136] = sA[buf][0];
        const float (*Al)[136] = sA[buf][1];
        const float (*Bh)[136] = sB[buf][0];
        const float (*Bl)[136] = sB[buf][1];

        uint32_t ah[4][4], al[4][4], bh[4][2], bl[4][2];
#pragma unroll
        for (int mt = 0; mt < 4; mt++) {
            const int r = warpM * 64 + mt * 16 + gid;
            ah[mt][0] = __float_as_uint(Ah[tig    ][r    ]);
            ah[mt][1] = __float_as_uint(Ah[tig    ][r + 8]);
            ah[mt][2] = __float_as_uint(Ah[tig + 4][r    ]);
            ah[mt][3] = __float_as_uint(Ah[tig + 4][r + 8]);
            al[mt][0] = __float_as_uint(Al[tig    ][r    ]);
            al[mt][1] = __float_as_uint(Al[tig    ][r + 8]);
            al[mt][2] = __float_as_uint(Al[tig + 4][r    ]);
            al[mt][3] = __float_as_uint(Al[tig + 4][r + 8]);
        }
#pragma unroll
        for (int nt = 0; nt < 4; nt++) {
            const int c = warpN * 32 + nt * 8 + gid;
            bh[nt][0] = __float_as_uint(Bh[tig    ][c]);
            bh[nt][1] = __float_as_uint(Bh[tig + 4][c]);
            bl[nt][0] = __float_as_uint(Bl[tig    ][c]);
            bl[nt][1] = __float_as_uint(Bl[tig + 4][c]);
        }

#pragma unroll
        for (int mt = 0; mt < 4; mt++)
#pragma unroll
            for (int nt = 0; nt < 4; nt++) {
                mma_tf32(acc[mt][nt], ah[mt][0], ah[mt][1], ah[mt][2], ah[mt][3],
                         bh[nt][0], bh[nt][1]);
                mma_tf32(acc[mt][nt], ah[mt][0], ah[mt][1], ah[mt][2], ah[mt][3],
                         bl[nt][0], bl[nt][1]);
                mma_tf32(acc[mt][nt], al[mt][0], al[mt][1], al[mt][2], al[mt][3],
                         bh[nt][0], bh[nt][1]);
            }

        if (hasNext) {
            const int nb = buf ^ 1;
            float h, l;
            split_tf32(av.x, h, l); sA[nb][0][aCol+0][aRow] = h; sA[nb][1][aCol+0][aRow] = l;
            split_tf32(av.y, h, l); sA[nb][0][aCol+1][aRow] = h; sA[nb][1][aCol+1][aRow] = l;
            split_tf32(av.z, h, l); sA[nb][0][aCol+2][aRow] = h; sA[nb][1][aCol+2][aRow] = l;
            split_tf32(av.w, h, l); sA[nb][0][aCol+3][aRow] = h; sA[nb][1][aCol+3][aRow] = l;
            float4 bhh, bll;
            split_tf32(bv.x, bhh.x, bll.x); split_tf32(bv.y, bhh.y, bll.y);
            split_tf32(bv.z, bhh.z, bll.z); split_tf32(bv.w, bhh.w, bll.w);
            *(float4*)&sB[nb][0][bRow][bCol] = bhh;
            *(float4*)&sB[nb][1][bRow][bCol] = bll;
        }
        __syncthreads();
    }

#pragma unroll
    for (int mt = 0; mt < 4; mt++) {
        const int row0 = mbase + warpM * 64 + mt * 16 + gid;
#pragma unroll
        for (int nt = 0; nt < 4; nt++) {
            const int col = nbase + warpN * 32 + nt * 8 + tig * 2;
            if (!GUARD || col < Nv) {
                float2 v0 = make_float2(acc[mt][nt][0], acc[mt][nt][1]);
                float2 v1 = make_float2(acc[mt][nt][2], acc[mt][nt][3]);
                if (ADDRES) {
                    float2 r0 = *(const float2*)(Res + (size_t)row0 * Nv + col);
                    float2 r1 = *(const float2*)(Res + (size_t)(row0 + 8) * Nv + col);
                    v0.x += r0.x; v0.y += r0.y; v1.x += r1.x; v1.y += r1.y;
                }
                *(float2*)(C + (size_t)row0 * Nv + col)       = v0;
                *(float2*)(C + (size_t)(row0 + 8) * Nv + col) = v1;
            }
        }
    }
}

__global__ void __launch_bounds__(256) gemm1_kernel(const float* __restrict__ A,
                                                    const float* __restrict__ W)
{
    gemm_tf32_body<3088, 512, true, false>(A, W, g_zx, nullptr);
}

__global__ void __launch_bounds__(256) gemm2_kernel(const float* __restrict__ W,
                                                    const float* __restrict__ Res)
{
    gemm_tf32_body<512, 1024, false, true>(g_g, W, g_res, Res);
}

// ---------------- K_G: G = Chat @ Bhat^T per (b,chunk) ----------------------------
// A = Chat [256,128] row-major (g_CmT chunk block), B = Bhat [256,128] row-major.
// G[tq][sq] = sum_n Chat[tq][n]*Bhat[sq][n]. TF32 3-pass. Tile 128x128, grid (2,2,128).
__global__ void __launch_bounds__(256) gscore_kernel()
{
    __shared__ __align__(16) float sA[2][2][8][136];
    __shared__ __align__(16) float sB[2][2][8][136];

    const int tid   = threadIdx.x;
    const int warp  = tid >> 5;
    const int lane  = tid & 31;
    const int gid   = lane >> 2;
    const int tig   = lane & 3;
    const int warpM = warp & 1;
    const int warpN = warp >> 1;
    const int ldRow = tid >> 1;        // 0..127
    const int ldCol = (tid & 1) * 4;   // 0 or 4

    const int bc    = blockIdx.z;
    const int nbase = blockIdx.x * 128;
    const int mbase = blockIdx.y * 128;
    const float* Ap = g_CmT + (size_t)bc * 32768 + (size_t)(mbase + ldRow) * 128 + ldCol;
    const float* Bp = g_BmT + (size_t)bc * 32768 + (size_t)(nbase + ldRow) * 128 + ldCol;
    float* Cp = g_G + (size_t)bc * 65536;

    float acc[4][4][4];
#pragma unroll
    for (int mt = 0; mt < 4; mt++)
#pragma unroll
        for (int nt = 0; nt < 4; nt++)
#pragma unroll
            for (int i = 0; i < 4; i++) acc[mt][nt][i] = 0.f;

    {
        float4 av = *(const float4*)Ap;
        float4 bv = *(const float4*)Bp;
        float h, l;
        split_tf32(av.x, h, l); sA[0][0][ldCol+0][ldRow] = h; sA[0][1][ldCol+0][ldRow] = l;
        split_tf32(av.y, h, l); sA[0][0][ldCol+1][ldRow] = h; sA[0][1][ldCol+1][ldRow] = l;
        split_tf32(av.z, h, l); sA[0][0][ldCol+2][ldRow] = h; sA[0][1][ldCol+2][ldRow] = l;
        split_tf32(av.w, h, l); sA[0][0][ldCol+3][ldRow] = h; sA[0][1][ldCol+3][ldRow] = l;
        split_tf32(bv.x, h, l); sB[0][0][ldCol+0][ldRow] = h; sB[0][1][ldCol+0][ldRow] = l;
        split_tf32(bv.y, h, l); sB[0][0][ldCol+1][ldRow] = h; sB[0][1][ldCol+1][ldRow] = l;
        split_tf32(bv.z, h, l); sB[0][0][ldCol+2][ldRow] = h; sB[0][1][ldCol+2][ldRow] = l;
        split_tf32(bv.w, h, l); sB[0][0][ldCol+3][ldRow] = h; sB[0][1][ldCol+3][ldRow] = l;
    }
    __syncthreads();

    for (int ks = 0; ks < 16; ks++) {
        const int buf = ks & 1;
        float4 av, bv;
        const bool hasNext = (ks + 1 < 16);
        if (hasNext) {
            av = *(const float4*)(Ap + (ks + 1) * 8);
            bv = *(const float4*)(Bp + (ks + 1) * 8);
        }

        const float (*Ah)[136] = sA[buf][0];
        const float (*Al)[136] = sA[buf][1];
        const float (*Bh)[136] = sB[buf][0];
        const float (*Bl)[136] = sB[buf][1];

        uint32_t ah[4][4], al[4][4], bh[4][2], bl[4][2];
#pragma unroll
        for (int mt = 0; mt < 4; mt++) {
            const int r = warpM * 64 + mt * 16 + gid;
            ah[mt][0] = __float_as_uint(Ah[tig    ][r    ]);
            ah[mt][1] = __float_as_uint(Ah[tig    ][r + 8]);
            ah[mt][2] = __float_as_uint(Ah[tig + 4][r    ]);
            ah[mt][3] = __float_as_uint(Ah[tig + 4][r + 8]);
            al[mt][0] = __float_as_uint(Al[tig    ][r    ]);
            al[mt][1] = __float_as_uint(Al[tig    ][r + 8]);
            al[mt][2] = __float_as_uint(Al[tig + 4][r    ]);
            al[mt][3] = __float_as_uint(Al[tig + 4][r + 8]);
        }
#pragma unroll
        for (int nt = 0; nt < 4; nt++) {
            const int c = warpN * 32 + nt * 8 + gid;
            bh[nt][0] = __float_as_uint(Bh[tig    ][c]);
            bh[nt][1] = __float_as_uint(Bh[tig + 4][c]);
            bl[nt][0] = __float_as_uint(Bl[tig    ][c]);
            bl[nt][1] = __float_as_uint(Bl[tig + 4][c]);
        }

#pragma unroll
        for (int mt = 0; mt < 4; mt++)
#pragma unroll
            for (int nt = 0; nt < 4; nt++) {
                mma_tf32(acc[mt][nt], ah[mt][0], ah[mt][1], ah[mt][2], ah[mt][3],
                         bh[nt][0], bh[nt][1]);
                mma_tf32(acc[mt][nt], ah[mt][0], ah[mt][1], ah[mt][2], ah[mt][3],
                         bl[nt][0], bl[nt][1]);
                mma_tf32(acc[mt][nt], al[mt][0], al[mt][1], al[mt][2], al[mt][3],
                         bh[nt][0], bh[nt][1]);
            }

        if (hasNext) {
            const int nb = buf ^ 1;
            float h, l;
            split_tf32(av.x, h, l); sA[nb][0][ldCol+0][ldRow] = h; sA[nb][1][ldCol+0][ldRow] = l;
            split_tf32(av.y, h, l); sA[nb][0][ldCol+1][ldRow] = h; sA[nb][1][ldCol+1][ldRow] = l;
            split_tf32(av.z, h, l); sA[nb][0][ldCol+2][ldRow] = h; sA[nb][1][ldCol+2][ldRow] = l;
            split_tf32(av.w, h, l); sA[nb][0][ldCol+3][ldRow] = h; sA[nb][1][ldCol+3][ldRow] = l;
            split_tf32(bv.x, h, l); sB[nb][0][ldCol+0][ldRow] = h; sB[nb][1][ldCol+0][ldRow] = l;
            split_tf32(bv.y, h, l); sB[nb][0][ldCol+1][ldRow] = h; sB[nb][1][ldCol+1][ldRow] = l;
            split_tf32(bv.z, h, l); sB[nb][0][ldCol+2][ldRow] = h; sB[nb][1][ldCol+2][ldRow] = l;
            split_tf32(bv.w, h, l); sB[nb][0][ldCol+3][ldRow] = h; sB[nb][1][ldCol+3][ldRow] = l;
        }
        __syncthreads();
    }

#pragma unroll
    for (int mt = 0; mt < 4; mt++) {
        const int row0 = mbase + warpM * 64 + mt * 16 + gid;
#pragma unroll
        for (int nt = 0; nt < 4; nt++) {
            const int col = nbase + warpN * 32 + nt * 8 + tig * 2;
            *(float2*)(Cp + (size_t)row0 * 256 + col)       = make_float2(acc[mt][nt][0], acc[mt][nt][1]);
            *(float2*)(Cp + (size_t)(row0 + 8) * 256 + col) = make_float2(acc[mt][nt][2], acc[mt][nt][3]);
        }
    }
}

// ---------------- conv1d (K=4, causal) + bias + silu + split ----------------------
__global__ void conv_kernel(const float* __restrict__ conv_w,
                            const float* __restrict__ conv_b)
{
    const int idx = blockIdx.x * blockDim.x + threadIdx.x; // [0, 8192*2048)
    const int c   = idx & 2047;
    const int row = idx >> 11;
    const int t   = row & (LL - 1);
    float acc = conv_b[c];
#pragma unroll
    for (int k = 0; k < 4; k++) {
        const int tt = t - 3 + k;
        if (tt >= 0)
            acc = fmaf(g_zx[(size_t)(row - (3 - k)) * 3088 + 1024 + c], conv_w[c * 4 + k], acc);
    }
    const float v = acc / (1.f + expf(-acc)); // silu
    if (c < 1024)       g_X[(size_t)row * 1024 + c] = v;
    else if (c < 1536) {
        const int i = c - 1024;   // n*4 + r
        g_BmT[(size_t)row * 512 + (i & 3) * 128 + (i >> 2)] = v;
    } else {
        const int i = c - 1536;   // n*4 + r
        g_CmT[(size_t)row * 512 + (i & 3) * 128 + (i >> 2)] = v;
    }
}

// ---------------- dt / logdec (head-major) ----------------------------------------
__global__ void dt_kernel(const float* __restrict__ dt_bias,
                          const float* __restrict__ A_log)
{
    const int idx = blockIdx.x * blockDim.x + threadIdx.x; // [0, 8192*16)
    const int h   = idx & 15;
    const int row = idx >> 4;
    const int b   = row >> 11;
    const int t   = row & (LL - 1);
    const float x  = g_zx[(size_t)row * 3088 + 3072 + h] + dt_bias[h];
    const float dt = (x > 20.f) ? x : log1pf(expf(x));
    const size_t o = ((size_t)b * 16 + h) * LL + t;
    g_dth[o] = dt;
    g_La [o] = -expf(A_log[h]) * dt;   // logdec; cumsum'd per chunk next
}

// ---------------- chunk-local inclusive cumsum of logdec --------------------------
// 2048 warps, one per (b,h,chunk) segment of 64.
__global__ void __launch_bounds__(256) cumsum_kernel()
{
    const int gw   = blockIdx.x * 8 + (threadIdx.x >> 5);  // 0..2047
    const int lane = threadIdx.x & 31;
    const int c    = gw & (NCHUNK - 1);
    const int bh   = gw >> 5;
    float* base = g_La + (size_t)bh * LL + c * QC;
    float v0 = base[2 * lane];
    float v1 = base[2 * lane + 1];
    float s  = v0 + v1;
#pragma unroll
    for (int o = 1; o < 32; o <<= 1) {
        float other = __shfl_up_sync(0xffffffffu, s, o);
        if (lane >= o) s += other;
    }
    const float excl = s - (v0 + v1);
    base[2 * lane]     = excl + v0;
    base[2 * lane + 1] = excl + v0 + v1;
}

// ---------------- K_P: per-chunk state contribution -------------------------------
// P[n,p] = sum_sq Bhat[sq,n] * wend[s] * Xhat[sq,p],  wend[s]=exp(La63-La[s])*dt[s].
// Grid 2048 = (b,c,h) with h fastest; 256 threads: thread owns (n = tid>>1, 8 p's).
__global__ void __launch_bounds__(256) pstate_kernel()
{
    const int bx = blockIdx.x;
    const int hh = bx & 15;
    const int cc = (bx >> 4) & (NCHUNK - 1);
    const int bb = bx >> 9;
    const int tid = threadIdx.x;

    __shared__ __align__(16) float sX[256][16];
    __shared__ float sW[64];

    const int brow = bb * LL + cc * QC;
    {   // stage Xhat: thread -> (s = tid>>2, quarter q = tid&3) loads 16 floats
        const int s = tid >> 2, q = tid & 3;
        const float4* src = (const float4*)(g_X + (size_t)(brow + s) * 1024 + hh * 64 + q * 16);
        float4* dst = (float4*)&sX[(s << 2) | q][0];
#pragma unroll
        for (int i = 0; i < 4; i++) dst[i] = src[i];
    }
    if (tid < 64) {
        const float* Lab = g_La  + ((size_t)bb * 16 + hh) * LL + cc * QC;
        const float* Dtb = g_dth + ((size_t)bb * 16 + hh) * LL + cc * QC;
        sW[tid] = expf(Lab[63] - Lab[tid]) * Dtb[tid];
    }
    __syncthreads();

    const int n  = tid >> 1;
    const int ph = tid & 1;
    float a[8];
#pragma unroll
    for (int i = 0; i < 8; i++) a[i] = 0.f;

    const float* Bb = g_BmT + (size_t)brow * 512 + n;
    for (int s = 0; s < QC; s++) {
        const float w = sW[s];
#pragma unroll
        for (int rp = 0; rp < 4; rp++) {
            const float bw = __ldg(Bb + (size_t)s * 512 + rp * 128) * w;
            const float4 x0 = *(const float4*)&sX[s * 4 + rp][ph * 8];
            const float4 x1 = *(const float4*)&sX[s * 4 + rp][ph * 8 + 4];
            a[0] = fmaf(bw, x0.x, a[0]); a[1] = fmaf(bw, x0.y, a[1]);
            a[2] = fmaf(bw, x0.z, a[2]); a[3] = fmaf(bw, x0.w, a[3]);
            a[4] = fmaf(bw, x1.x, a[4]); a[5] = fmaf(bw, x1.y, a[5]);
            a[6] = fmaf(bw, x1.z, a[6]); a[7] = fmaf(bw, x1.w, a[7]);
        }
    }
    float* Pp = g_P + (size_t)bx * 2048 + n * 16 + ph * 8;
    *(float4*)Pp       = make_float4(a[0], a[1], a[2], a[3]);
    *(float4*)(Pp + 4) = make_float4(a[4], a[5], a[6], a[7]);
}

// ---------------- K_carry: sequential chunk-state chain ---------------------------
// Grid 64 = (b,h); 256 threads own 8 state elements each. S[c] stored BEFORE chunk c.
__global__ void __launch_bounds__(256) carry_kernel()
{
    const int bx = blockIdx.x;     // b*16+h
    const int bb = bx >> 4;
    const int hh = bx & 15;
    const int off = threadIdx.x * 8;
    const float* Lab = g_La + ((size_t)bb * 16 + hh) * LL;

    float4 s0 = make_float4(0.f,0.f,0.f,0.f);
    float4 s1 = make_float4(0.f,0.f,0.f,0.f);
    for (int c = 0; c < NCHUNK; c++) {
        const size_t slot = ((size_t)(bb * NCHUNK + c) * 16 + hh) * 2048 + off;
        *(float4*)(g_S + slot)     = s0;
        *(float4*)(g_S + slot + 4) = s1;
        const float ef = expf(Lab[c * QC + 63]);
        const float4 p0 = *(const float4*)(g_P + slot);
        const float4 p1 = *(const float4*)(g_P + slot + 4);
        s0.x = fmaf(ef, s0.x, p0.x); s0.y = fmaf(ef, s0.y, p0.y);
        s0.z = fmaf(ef, s0.z, p0.z); s0.w = fmaf(ef, s0.w, p0.w);
        s1.x = fmaf(ef, s1.x, p1.x); s1.y = fmaf(ef, s1.y, p1.y);
        s1.z = fmaf(ef, s1.z, p1.z); s1.w = fmaf(ef, s1.w, p1.w);
    }
}

// ---------------- K_y: y = inter + intra, fused D_skip + z-gate -------------------
// Grid 2048 = (b,c,h); 256 threads, thread = tq = (t,r), owns 16 p outputs.
__global__ void __launch_bounds__(256) yout_kernel(const float* __restrict__ D_skip)
{
    const int bx = blockIdx.x;
    const int hh = bx & 15;
    const int cc = (bx >> 4) & (NCHUNK - 1);
    const int bb = bx >> 9;
    const int tid = threadIdx.x;
    const int t = tid >> 2;
    const int r = tid & 3;

    __shared__ __align__(16) float sX[256][16];
    __shared__ __align__(16) float sS[128][16];
    __shared__ float sLa[64], sDt[64];

    const int brow = bb * LL + cc * QC;
    {   // stage Xhat
        const int s = tid >> 2, q = tid & 3;
        const float4* src = (const float4*)(g_X + (size_t)(brow + s) * 1024 + hh * 64 + q * 16);
        float4* dst = (float4*)&sX[(s << 2) | q][0];
#pragma unroll
        for (int i = 0; i < 4; i++) dst[i] = src[i];
    }
    {   // stage S_start (2048 floats)
        const float4* src = (const float4*)(g_S + (size_t)bx * 2048 + tid * 8);
        float4* dst = (float4*)(&sS[0][0] + tid * 8);
        dst[0] = src[0]; dst[1] = src[1];
    }
    if (tid < 64) {
        sLa[tid] = g_La [((size_t)bb * 16 + hh) * LL + cc * QC + tid];
        sDt[tid] = g_dth[((size_t)bb * 16 + hh) * LL + cc * QC + tid];
    }
    __syncthreads();

    float acc[16];
#pragma unroll
    for (int i = 0; i < 16; i++) acc[i] = 0.f;

    // ---- inter-chunk: (Chat @ S_start) scaled by exp(La[t]) ----
    const float4* crow = (const float4*)(g_CmT + (size_t)(brow + t) * 512 + r * 128);
    for (int nq = 0; nq < 32; nq++) {
        const float4 cv = __ldg(crow + nq);
#pragma unroll
        for (int j = 0; j < 4; j++) {
            const float cn = (j == 0) ? cv.x : (j == 1) ? cv.y : (j == 2) ? cv.z : cv.w;
            const float* sr = &sS[nq * 4 + j][0];
#pragma unroll
            for (int p = 0; p < 16; p++) acc[p] = fmaf(cn, sr[p], acc[p]);
        }
    }
    const float lat = sLa[t];
    const float einter = expf(lat);
#pragma unroll
    for (int p = 0; p < 16; p++) acc[p] *= einter;

    // ---- intra-chunk: sum_{s<=t} w(t,s) * G[tq][4s+r'] * Xhat[4s+r'][p] ----
    const float4* Gp = (const float4*)(g_G + (size_t)(bb * NCHUNK + cc) * 65536 + (size_t)tid * 256);
    for (int s = 0; s <= t; s++) {
        const float w = expf(lat - sLa[s]) * sDt[s];
        const float4 gv = __ldg(Gp + s);
        const float g0 = gv.x * w, g1 = gv.y * w, g2 = gv.z * w, g3 = gv.w * w;
        const float* x0 = &sX[s * 4 + 0][0];
        const float* x1 = &sX[s * 4 + 1][0];
        const float* x2 = &sX[s * 4 + 2][0];
        const float* x3 = &sX[s * 4 + 3][0];
#pragma unroll
        for (int p = 0; p < 16; p++) {
            float v = fmaf(g0, x0[p], acc[p]);
            v = fmaf(g1, x1[p], v);
            v = fmaf(g2, x2[p], v);
            acc[p] = fmaf(g3, x3[p], v);
        }
    }

    // ---- epilogue: + x*D_skip, gate with silu(z), write g_g ----
    const float dsk = D_skip[hh];
    const int row = brow + t;
    const float* xv = &sX[tid][0];
    float* go = g_g + (size_t)row * 1024 + hh * 64 + r * 16;
    const float* zp = g_zx + (size_t)row * 3088 + hh * 64 + r * 16;
#pragma unroll
    for (int p = 0; p < 16; p++) {
        const float y = fmaf(xv[p], dsk, acc[p]);
        const float z = zp[p];
        go[p] = y * (z / (1.f + expf(-z)));
    }
}

// ---------------- RMSNorm ---------------------------------------------------------
__global__ void __launch_bounds__(256) rms_kernel(float* __restrict__ out)
{
    const int warp = threadIdx.x >> 5;
    const int lane = threadIdx.x & 31;
    const int row  = blockIdx.x * 8 + warp;
    const float* r = g_res + (size_t)row * 512;
    float v[16];
    float ss = 0.f;
#pragma unroll
    for (int i = 0; i < 16; i++) { v[i] = r[lane + i * 32]; ss = fmaf(v[i], v[i], ss); }
#pragma unroll
    for (int o = 16; o >= 1; o >>= 1) ss += __shfl_xor_sync(0xffffffffu, ss, o);
    const float sc = rsqrtf(ss * (1.f / 512.f) + 1e-5f);
    float* o = out + (size_t)row * 512;
#pragma unroll
    for (int i = 0; i < 16; i++) o[lane + i * 32] = v[i] * sc;
}

// ---------------- launch ----------------------------------------------------------
extern "C" void kernel_launch(void* const* d_in, const int* in_sizes, int n_in,
                              void* d_out, int out_size)
{
    const float* hs      = (const float*)d_in[0];
    const float* W_in    = (const float*)d_in[1];
    const float* conv_w  = (const float*)d_in[2];
    const float* conv_b  = (const float*)d_in[3];
    const float* dt_bias = (const float*)d_in[4];
    const float* A_log   = (const float*)d_in[5];
    const float* D_skip  = (const float*)d_in[6];
    const float* W_out   = (const float*)d_in[7];
    float* out = (float*)d_out;

    gemm1_kernel<<<dim3(25, 64), 256>>>(hs, W_in);
    conv_kernel<<<NROWS * 2048 / 256, 256>>>(conv_w, conv_b);
    dt_kernel<<<NROWS * 16 / 256, 256>>>(dt_bias, A_log);
    cumsum_kernel<<<256, 256>>>();
    gscore_kernel<<<dim3(2, 2, 128), 256>>>();
    pstate_kernel<<<2048, 256>>>();
    carry_kernel<<<64, 256>>>();
    yout_kernel<<<2048, 256>>>(D_skip);
    gemm2_kernel<<<dim3(4, 64), 256>>>(W_out, hs);
    rms_kernel<<<NROWS / 8, 256>>>(out);
}

// round 12
// speedup vs baseline: 1.9382x; 1.2645x over previous
#include <cuda_runtime.h>
#include <math.h>
#include <stdint.h>

#define LL 2048
#define NROWS 8192   // B*L
#define QC 64        // chunk length
#define NCHUNK 32    // chunks per batch

// ---------------- scratch (device globals; no runtime allocation) ----------------
static __device__ float g_zx [NROWS * 3088]; // zxbcdt
static __device__ float g_X  [NROWS * 1024]; // silu(conv) x part [row][h*64+r*16+p]
static __device__ float g_BmT[NROWS * 512];  // B^T [row][r*128+n]
static __device__ float g_CmT[NROWS * 512];  // C^T [row][r*128+n]
static __device__ float g_dth[4 * 16 * LL];  // dt  [b,h,t]
static __device__ float g_La [4 * 16 * LL];  // chunk-local cumsum(logdec) [b,h,t]
static __device__ float g_G  [128 * 65536];  // scores [b*32+c][tq*256+sq]
static __device__ float g_P  [2048 * 2048];  // chunk state contrib [(b*32+c)*16+h][n*16+p]
static __device__ float g_S  [2048 * 2048];  // chunk-start states, same layout
static __device__ float g_g  [NROWS * 1024]; // gated
static __device__ float g_res[NROWS * 512];  // pre-norm residual

// ---------------- tf32 helpers (used by gscore) ------------------------------------
__device__ __forceinline__ uint32_t f2tf32(float v) {
    uint32_t r;
    asm("cvt.rna.tf32.f32 %0, %1;" : "=r"(r) : "f"(v));
    return r;
}
__device__ __forceinline__ void split_tf32(float v, float& hi, float& lo) {
    uint32_t h = f2tf32(v);
    hi = __uint_as_float(h);
    float l = v - hi;                 // exact in fp32
    lo = __uint_as_float(f2tf32(l));
}
__device__ __forceinline__ void mma_tf32(float d[4],
                                         uint32_t a0, uint32_t a1, uint32_t a2, uint32_t a3,
                                         uint32_t b0, uint32_t b1) {
    asm volatile(
        "mma.sync.aligned.m16n8k8.row.col.f32.tf32.tf32.f32 "
        "{%0,%1,%2,%3}, {%4,%5,%6,%7}, {%8,%9}, {%0,%1,%2,%3};"
        : "+f"(d[0]), "+f"(d[1]), "+f"(d[2]), "+f"(d[3])
        : "r"(a0), "r"(a1), "r"(a2), "r"(a3), "r"(b0), "r"(b1));
}

// ---------------- bf16 helpers ------------------------------------------------------
// Pack pair (x0 -> low half / even k, x1 -> high half / odd k); hi/lo split.
// lo = x - bf16(x) is exact in fp32; |lo| <= 2^-9 |x|.
__device__ __forceinline__ void bsplit2(float x0, float x1, uint32_t& hi, uint32_t& lo) {
    asm("cvt.rn.bf16x2.f32 %0, %2, %1;" : "=r"(hi) : "f"(x0), "f"(x1));
    const float h0 = __uint_as_float(hi << 16);
    const float h1 = __uint_as_float(hi & 0xffff0000u);
    const float l0 = x0 - h0;
    const float l1 = x1 - h1;
    asm("cvt.rn.bf16x2.f32 %0, %2, %1;" : "=r"(lo) : "f"(l0), "f"(l1));
}
__device__ __forceinline__ void mma_bf16(float d[4],
                                         uint32_t a0, uint32_t a1, uint32_t a2, uint32_t a3,
                                         uint32_t b0, uint32_t b1) {
    asm volatile(
        "mma.sync.aligned.m16n8k16.row.col.f32.bf16.bf16.f32 "
        "{%0,%1,%2,%3}, {%4,%5,%6,%7}, {%8,%9}, {%0,%1,%2,%3};"
        : "+f"(d[0]), "+f"(d[1]), "+f"(d[2]), "+f"(d[3])
        : "r"(a0), "r"(a1), "r"(a2), "r"(a3), "r"(b0), "r"(b1));
}

// ---------------- BF16 3-pass tensor-core GEMM: C = A(MxK) @ B(KxN) [+ Res] --------
// CTA tile 128x128, 8 warps (2M x 4N -> 64x32 warp tiles). k-slab = 16 per stage.
// smem: bf16x2 words, k-pairs packed; [buf][hi/lo][k2][entry], stride 136 words
// -> fragment loads conflict-free (bank = (8*tig + gid + c) mod 32 covers all banks).
template<int Nv, int Kv, bool GUARD, bool ADDRES>
__device__ __forceinline__ void gemm_bf16_body(const float* __restrict__ A,
                                               const float* __restrict__ Bw,
                                               float* __restrict__ C,
                                               const float* __restrict__ Res)
{
    __shared__ __align__(16) uint32_t sA[2][2][8][136]; // [buf][hi/lo][k2][row]
    __shared__ __align__(16) uint32_t sB[2][2][8][136]; // [buf][hi/lo][k2][col]

    const int tid   = threadIdx.x;
    const int warp  = tid >> 5;
    const int lane  = tid & 31;
    const int gid   = lane >> 2;   // 0..7
    const int tig   = lane & 3;    // 0..3
    const int warpM = warp & 1;
    const int warpN = warp >> 1;

    const int aRow = tid >> 1;          // 0..127
    const int aK2  = (tid & 1) * 4;     // pair-base 0 or 4 (k offset 0 or 8)
    const int bK2  = tid >> 5;          // 0..7 (k-pair row)
    const int bCol = (tid & 31) * 4;    // 0..124

    const int nbase = blockIdx.x * 128;
    const int mbase = blockIdx.y * 128;
    const float* Ap  = A + (size_t)(mbase + aRow) * Kv + aK2 * 2;
    const float* Bp0 = Bw + (size_t)(2 * bK2) * Nv + nbase + bCol;
    const float* Bp1 = Bp0 + Nv;
    const bool  bOK = (!GUARD) || (nbase + bCol + 3 < Nv);

    float acc[4][4][4];
#pragma unroll
    for (int mt = 0; mt < 4; mt++)
#pragma unroll
        for (int nt = 0; nt < 4; nt++)
#pragma unroll
            for (int i = 0; i < 4; i++) acc[mt][nt][i] = 0.f;

    // ---- stage 0 fill ----
    {
        float4 av0 = *(const float4*)Ap;
        float4 av1 = *(const float4*)(Ap + 4);
        float4 bv0 = bOK ? *(const float4*)Bp0 : make_float4(0.f,0.f,0.f,0.f);
        float4 bv1 = bOK ? *(const float4*)Bp1 : make_float4(0.f,0.f,0.f,0.f);
        uint32_t h, l;
        bsplit2(av0.x, av0.y, h, l); sA[0][0][aK2+0][aRow] = h; sA[0][1][aK2+0][aRow] = l;
        bsplit2(av0.z, av0.w, h, l); sA[0][0][aK2+1][aRow] = h; sA[0][1][aK2+1][aRow] = l;
        bsplit2(av1.x, av1.y, h, l); sA[0][0][aK2+2][aRow] = h; sA[0][1][aK2+2][aRow] = l;
        bsplit2(av1.z, av1.w, h, l); sA[0][0][aK2+3][aRow] = h; sA[0][1][aK2+3][aRow] = l;
        uint32_t hw[4], lw[4];
        bsplit2(bv0.x, bv1.x, hw[0], lw[0]);
        bsplit2(bv0.y, bv1.y, hw[1], lw[1]);
        bsplit2(bv0.z, bv1.z, hw[2], lw[2]);
        bsplit2(bv0.w, bv1.w, hw[3], lw[3]);
        *(uint4*)&sB[0][0][bK2][bCol] = make_uint4(hw[0], hw[1], hw[2], hw[3]);
        *(uint4*)&sB[0][1][bK2][bCol] = make_uint4(lw[0], lw[1], lw[2], lw[3]);
    }
    __syncthreads();

    const int NK = Kv / 16;
    for (int ks = 0; ks < NK; ks++) {
        const int buf = ks & 1;
        float4 av0, av1, bv0, bv1;
        const bool hasNext = (ks + 1 < NK);
        if (hasNext) {
            av0 = *(const float4*)(Ap + (ks + 1) * 16);
            av1 = *(const float4*)(Ap + (ks + 1) * 16 + 4);
            bv0 = bOK ? *(const float4*)(Bp0 + (size_t)(ks + 1) * 16 * Nv)
                      : make_float4(0.f,0.f,0.f,0.f);
            bv1 = bOK ? *(const float4*)(Bp1 + (size_t)(ks + 1) * 16 * Nv)
                      : make_float4(0.f,0.f,0.f,0.f);
        }

        const uint32_t (*Ah)[136] = sA[buf][0];
        const uint32_t (*Al)[136] = sA[buf][1];
        const uint32_t (*Bh)[136] = sB[buf][0];
        const uint32_t (*Bl)[136] = sB[buf][1];

        uint32_t ah[4][4], al[4][4], bh[4][2], bl[4][2];
#pragma unroll
        for (int mt = 0; mt < 4; mt++) {
            const int r = warpM * 64 + mt * 16 + gid;
            ah[mt][0] = Ah[tig    ][r    ];
            ah[mt][1] = Ah[tig    ][r + 8];
            ah[mt][2] = Ah[tig + 4][r    ];
            ah[mt][3] = Ah[tig + 4][r + 8];
            al[mt][0] = Al[tig    ][r    ];
            al[mt][1] = Al[tig    ][r + 8];
            al[mt][2] = Al[tig + 4][r    ];
            al[mt][3] = Al[tig + 4][r + 8];
        }
#pragma unroll
        for (int nt = 0; nt < 4; nt++) {
            const int c = warpN * 32 + nt * 8 + gid;
            bh[nt][0] = Bh[tig    ][c];
            bh[nt][1] = Bh[tig + 4][c];
            bl[nt][0] = Bl[tig    ][c];
            bl[nt][1] = Bl[tig + 4][c];
        }

        // ---- 3-pass mma: hi*hi + hi*lo + lo*hi ----
#pragma unroll
        for (int mt = 0; mt < 4; mt++)
#pragma unroll
            for (int nt = 0; nt < 4; nt++) {
                mma_bf16(acc[mt][nt], ah[mt][0], ah[mt][1], ah[mt][2], ah[mt][3],
                         bh[nt][0], bh[nt][1]);
                mma_bf16(acc[mt][nt], ah[mt][0], ah[mt][1], ah[mt][2], ah[mt][3],
                         bl[nt][0], bl[nt][1]);
                mma_bf16(acc[mt][nt], al[mt][0], al[mt][1], al[mt][2], al[mt][3],
                         bh[nt][0], bh[nt][1]);
            }

        if (hasNext) {
            const int nb = buf ^ 1;
            uint32_t h, l;
            bsplit2(av0.x, av0.y, h, l); sA[nb][0][aK2+0][aRow] = h; sA[nb][1][aK2+0][aRow] = l;
            bsplit2(av0.z, av0.w, h, l); sA[nb][0][aK2+1][aRow] = h; sA[nb][1][aK2+1][aRow] = l;
            bsplit2(av1.x, av1.y, h, l); sA[nb][0][aK2+2][aRow] = h; sA[nb][1][aK2+2][aRow] = l;
            bsplit2(av1.z, av1.w, h, l); sA[nb][0][aK2+3][aRow] = h; sA[nb][1][aK2+3][aRow] = l;
            uint32_t hw[4], lw[4];
            bsplit2(bv0.x, bv1.x, hw[0], lw[0]);
            bsplit2(bv0.y, bv1.y, hw[1], lw[1]);
            bsplit2(bv0.z, bv1.z, hw[2], lw[2]);
            bsplit2(bv0.w, bv1.w, hw[3], lw[3]);
            *(uint4*)&sB[nb][0][bK2][bCol] = make_uint4(hw[0], hw[1], hw[2], hw[3]);
            *(uint4*)&sB[nb][1][bK2][bCol] = make_uint4(lw[0], lw[1], lw[2], lw[3]);
        }
        __syncthreads();
    }

#pragma unroll
    for (int mt = 0; mt < 4; mt++) {
        const int row0 = mbase + warpM * 64 + mt * 16 + gid;
#pragma unroll
        for (int nt = 0; nt < 4; nt++) {
            const int col = nbase + warpN * 32 + nt * 8 + tig * 2;
            if (!GUARD || col < Nv) {
                float2 v0 = make_float2(acc[mt][nt][0], acc[mt][nt][1]);
                float2 v1 = make_float2(acc[mt][nt][2], acc[mt][nt][3]);
                if (ADDRES) {
                    float2 r0 = *(const float2*)(Res + (size_t)row0 * Nv + col);
                    float2 r1 = *(const float2*)(Res + (size_t)(row0 + 8) * Nv + col);
                    v0.x += r0.x; v0.y += r0.y; v1.x += r1.x; v1.y += r1.y;
                }
                *(float2*)(C + (size_t)row0 * Nv + col)       = v0;
                *(float2*)(C + (size_t)(row0 + 8) * Nv + col) = v1;
            }
        }
    }
}

__global__ void __launch_bounds__(256) gemm1_kernel(const float* __restrict__ A,
                                                    const float* __restrict__ W)
{
    gemm_bf16_body<3088, 512, true, false>(A, W, g_zx, nullptr);
}

__global__ void __launch_bounds__(256) gemm2_kernel(const float* __restrict__ W,
                                                    const float* __restrict__ Res)
{
    gemm_bf16_body<512, 1024, false, true>(g_g, W, g_res, Res);
}

// ---------------- K_G: G = Chat @ Bhat^T per (b,chunk), TF32 3-pass ---------------
__global__ void __launch_bounds__(256) gscore_kernel()
{
    __shared__ __align__(16) float sA[2][2][8][136];
    __shared__ __align__(16) float sB[2][2][8][136];

    const int tid   = threadIdx.x;
    const int warp  = tid >> 5;
    const int lane  = tid & 31;
    const int gid   = lane >> 2;
    const int tig   = lane & 3;
    const int warpM = warp & 1;
    const int warpN = warp >> 1;
    const int ldRow = tid >> 1;
    const int ldCol = (tid & 1) * 4;

    const int bc    = blockIdx.z;
    const int nbase = blockIdx.x * 128;
    const int mbase = blockIdx.y * 128;
    const float* Ap = g_CmT + (size_t)bc * 32768 + (size_t)(mbase + ldRow) * 128 + ldCol;
    const float* Bp = g_BmT + (size_t)bc * 32768 + (size_t)(nbase + ldRow) * 128 + ldCol;
    float* Cp = g_G + (size_t)bc * 65536;

    float acc[4][4][4];
#pragma unroll
    for (int mt = 0; mt < 4; mt++)
#pragma unroll
        for (int nt = 0; nt < 4; nt++)
#pragma unroll
            for (int i = 0; i < 4; i++) acc[mt][nt][i] = 0.f;

    {
        float4 av = *(const float4*)Ap;
        float4 bv = *(const float4*)Bp;
        float h, l;
        split_tf32(av.x, h, l); sA[0][0][ldCol+0][ldRow] = h; sA[0][1][ldCol+0][ldRow] = l;
        split_tf32(av.y, h, l); sA[0][0][ldCol+1][ldRow] = h; sA[0][1][ldCol+1][ldRow] = l;
        split_tf32(av.z, h, l); sA[0][0][ldCol+2][ldRow] = h; sA[0][1][ldCol+2][ldRow] = l;
        split_tf32(av.w, h, l); sA[0][0][ldCol+3][ldRow] = h; sA[0][1][ldCol+3][ldRow] = l;
        split_tf32(bv.x, h, l); sB[0][0][ldCol+0][ldRow] = h; sB[0][1][ldCol+0][ldRow] = l;
        split_tf32(bv.y, h, l); sB[0][0][ldCol+1][ldRow] = h; sB[0][1][ldCol+1][ldRow] = l;
        split_tf32(bv.z, h, l); sB[0][0][ldCol+2][ldRow] = h; sB[0][1][ldCol+2][ldRow] = l;
        split_tf32(bv.w, h, l); sB[0][0][ldCol+3][ldRow] = h; sB[0][1][ldCol+3][ldRow] = l;
    }
    __syncthreads();

    for (int ks = 0; ks < 16; ks++) {
        const int buf = ks & 1;
        float4 av, bv;
        const bool hasNext = (ks + 1 < 16);
        if (hasNext) {
            av = *(const float4*)(Ap + (ks + 1) * 8);
            bv = *(const float4*)(Bp + (ks + 1) * 8);
        }

        const float (*Ah)[136] = sA[buf][0];
        const float (*Al)[136] = sA[buf][1];
        const float (*Bh)[136] = sB[buf][0];
        const float (*Bl)[136] = sB[buf][1];

        uint32_t ah[4][4], al[4][4], bh[4][2], bl[4][2];
#pragma unroll
        for (int mt = 0; mt < 4; mt++) {
            const int r = warpM * 64 + mt * 16 + gid;
            ah[mt][0] = __float_as_uint(Ah[tig    ][r    ]);
            ah[mt][1] = __float_as_uint(Ah[tig    ][r + 8]);
            ah[mt][2] = __float_as_uint(Ah[tig + 4][r    ]);
            ah[mt][3] = __float_as_uint(Ah[tig + 4][r + 8]);
            al[mt][0] = __float_as_uint(Al[tig    ][r    ]);
            al[mt][1] = __float_as_uint(Al[tig    ][r + 8]);
            al[mt][2] = __float_as_uint(Al[tig + 4][r    ]);
            al[mt][3] = __float_as_uint(Al[tig + 4][r + 8]);
        }
#pragma unroll
        for (int nt = 0; nt < 4; nt++) {
            const int c = warpN * 32 + nt * 8 + gid;
            bh[nt][0] = __float_as_uint(Bh[tig    ][c]);
            bh[nt][1] = __float_as_uint(Bh[tig + 4][c]);
            bl[nt][0] = __float_as_uint(Bl[tig    ][c]);
            bl[nt][1] = __float_as_uint(Bl[tig + 4][c]);
        }

#pragma unroll
        for (int mt = 0; mt < 4; mt++)
#pragma unroll
            for (int nt = 0; nt < 4; nt++) {
                mma_tf32(acc[mt][nt], ah[mt][0], ah[mt][1], ah[mt][2], ah[mt][3],
                         bh[nt][0], bh[nt][1]);
                mma_tf32(acc[mt][nt], ah[mt][0], ah[mt][1], ah[mt][2], ah[mt][3],
                         bl[nt][0], bl[nt][1]);
                mma_tf32(acc[mt][nt], al[mt][0], al[mt][1], al[mt][2], al[mt][3],
                         bh[nt][0], bh[nt][1]);
            }

        if (hasNext) {
            const int nb = buf ^ 1;
            float h, l;
            split_tf32(av.x, h, l); sA[nb][0][ldCol+0][ldRow] = h; sA[nb][1][ldCol+0][ldRow] = l;
            split_tf32(av.y, h, l); sA[nb][0][ldCol+1][ldRow] = h; sA[nb][1][ldCol+1][ldRow] = l;
            split_tf32(av.z, h, l); sA[nb][0][ldCol+2][ldRow] = h; sA[nb][1][ldCol+2][ldRow] = l;
            split_tf32(av.w, h, l); sA[nb][0][ldCol+3][ldRow] = h; sA[nb][1][ldCol+3][ldRow] = l;
            split_tf32(bv.x, h, l); sB[nb][0][ldCol+0][ldRow] = h; sB[nb][1][ldCol+0][ldRow] = l;
            split_tf32(bv.y, h, l); sB[nb][0][ldCol+1][ldRow] = h; sB[nb][1][ldCol+1][ldRow] = l;
            split_tf32(bv.z, h, l); sB[nb][0][ldCol+2][ldRow] = h; sB[nb][1][ldCol+2][ldRow] = l;
            split_tf32(bv.w, h, l); sB[nb][0][ldCol+3][ldRow] = h; sB[nb][1][ldCol+3][ldRow] = l;
        }
        __syncthreads();
    }

#pragma unroll
    for (int mt = 0; mt < 4; mt++) {
        const int row0 = mbase + warpM * 64 + mt * 16 + gid;
#pragma unroll
        for (int nt = 0; nt < 4; nt++) {
            const int col = nbase + warpN * 32 + nt * 8 + tig * 2;
            *(float2*)(Cp + (size_t)row0 * 256 + col)       = make_float2(acc[mt][nt][0], acc[mt][nt][1]);
            *(float2*)(Cp + (size_t)(row0 + 8) * 256 + col) = make_float2(acc[mt][nt][2], acc[mt][nt][3]);
        }
    }
}

// ---------------- conv1d (K=4, causal) + bias + silu + split ----------------------
__global__ void conv_kernel(const float* __restrict__ conv_w,
                            const float* __restrict__ conv_b)
{
    const int idx = blockIdx.x * blockDim.x + threadIdx.x; // [0, 8192*2048)
    const int c   = idx & 2047;
    const int row = idx >> 11;
    const int t   = row & (LL - 1);
    float acc = conv_b[c];
#pragma unroll
    for (int k = 0; k < 4; k++) {
        const int tt = t - 3 + k;
        if (tt >= 0)
            acc = fmaf(g_zx[(size_t)(row - (3 - k)) * 3088 + 1024 + c], conv_w[c * 4 + k], acc);
    }
    const float v = acc / (1.f + expf(-acc)); // silu
    if (c < 1024)       g_X[(size_t)row * 1024 + c] = v;
    else if (c < 1536) {
        const int i = c - 1024;   // n*4 + r
        g_BmT[(size_t)row * 512 + (i & 3) * 128 + (i >> 2)] = v;
    } else {
        const int i = c - 1536;   // n*4 + r
        g_CmT[(size_t)row * 512 + (i & 3) * 128 + (i >> 2)] = v;
    }
}

// ---------------- dt / logdec (head-major) ----------------------------------------
__global__ void dt_kernel(const float* __restrict__ dt_bias,
                          const float* __restrict__ A_log)
{
    const int idx = blockIdx.x * blockDim.x + threadIdx.x; // [0, 8192*16)
    const int h   = idx & 15;
    const int row = idx >> 4;
    const int b   = row >> 11;
    const int t   = row & (LL - 1);
    const float x  = g_zx[(size_t)row * 3088 + 3072 + h] + dt_bias[h];
    const float dt = (x > 20.f) ? x : log1pf(expf(x));
    const size_t o = ((size_t)b * 16 + h) * LL + t;
    g_dth[o] = dt;
    g_La [o] = -expf(A_log[h]) * dt;   // logdec; cumsum'd per chunk next
}

// ---------------- chunk-local inclusive cumsum of logdec --------------------------
__global__ void __launch_bounds__(256) cumsum_kernel()
{
    const int gw   = blockIdx.x * 8 + (threadIdx.x >> 5);  // 0..2047
    const int lane = threadIdx.x & 31;
    const int c    = gw & (NCHUNK - 1);
    const int bh   = gw >> 5;
    float* base = g_La + (size_t)bh * LL + c * QC;
    float v0 = base[2 * lane];
    float v1 = base[2 * lane + 1];
    float s  = v0 + v1;
#pragma unroll
    for (int o = 1; o < 32; o <<= 1) {
        float other = __shfl_up_sync(0xffffffffu, s, o);
        if (lane >= o) s += other;
    }
    const float excl = s - (v0 + v1);
    base[2 * lane]     = excl + v0;
    base[2 * lane + 1] = excl + v0 + v1;
}

// ---------------- K_P: per-chunk state contribution -------------------------------
__global__ void __launch_bounds__(256) pstate_kernel()
{
    const int bx = blockIdx.x;
    const int hh = bx & 15;
    const int cc = (bx >> 4) & (NCHUNK - 1);
    const int bb = bx >> 9;
    const int tid = threadIdx.x;

    __shared__ __align__(16) float sX[256][16];
    __shared__ float sW[64];

    const int brow = bb * LL + cc * QC;
    {
        const int s = tid >> 2, q = tid & 3;
        const float4* src = (const float4*)(g_X + (size_t)(brow + s) * 1024 + hh * 64 + q * 16);
        float4* dst = (float4*)&sX[(s << 2) | q][0];
#pragma unroll
        for (int i = 0; i < 4; i++) dst[i] = src[i];
    }
    if (tid < 64) {
        const float* Lab = g_La  + ((size_t)bb * 16 + hh) * LL + cc * QC;
        const float* Dtb = g_dth + ((size_t)bb * 16 + hh) * LL + cc * QC;
        sW[tid] = expf(Lab[63] - Lab[tid]) * Dtb[tid];
    }
    __syncthreads();

    const int n  = tid >> 1;
    const int ph = tid & 1;
    float a[8];
#pragma unroll
    for (int i = 0; i < 8; i++) a[i] = 0.f;

    const float* Bb = g_BmT + (size_t)brow * 512 + n;
    for (int s = 0; s < QC; s++) {
        const float w = sW[s];
#pragma unroll
        for (int rp = 0; rp < 4; rp++) {
            const float bw = __ldg(Bb + (size_t)s * 512 + rp * 128) * w;
            const float4 x0 = *(const float4*)&sX[s * 4 + rp][ph * 8];
            const float4 x1 = *(const float4*)&sX[s * 4 + rp][ph * 8 + 4];
            a[0] = fmaf(bw, x0.x, a[0]); a[1] = fmaf(bw, x0.y, a[1]);
            a[2] = fmaf(bw, x0.z, a[2]); a[3] = fmaf(bw, x0.w, a[3]);
            a[4] = fmaf(bw, x1.x, a[4]); a[5] = fmaf(bw, x1.y, a[5]);
            a[6] = fmaf(bw, x1.z, a[6]); a[7] = fmaf(bw, x1.w, a[7]);
        }
    }
    float* Pp = g_P + (size_t)bx * 2048 + n * 16 + ph * 8;
    *(float4*)Pp       = make_float4(a[0], a[1], a[2], a[3]);
    *(float4*)(Pp + 4) = make_float4(a[4], a[5], a[6], a[7]);
}

// ---------------- K_carry: sequential chunk-state chain ---------------------------
__global__ void __launch_bounds__(256) carry_kernel()
{
    const int bx = blockIdx.x;     // b*16+h
    const int bb = bx >> 4;
    const int hh = bx & 15;
    const int off = threadIdx.x * 8;
    const float* Lab = g_La + ((size_t)bb * 16 + hh) * LL;

    float4 s0 = make_float4(0.f,0.f,0.f,0.f);
    float4 s1 = make_float4(0.f,0.f,0.f,0.f);
    for (int c = 0; c < NCHUNK; c++) {
        const size_t slot = ((size_t)(bb * NCHUNK + c) * 16 + hh) * 2048 + off;
        *(float4*)(g_S + slot)     = s0;
        *(float4*)(g_S + slot + 4) = s1;
        const float ef = expf(Lab[c * QC + 63]);
        const float4 p0 = *(const float4*)(g_P + slot);
        const float4 p1 = *(const float4*)(g_P + slot + 4);
        s0.x = fmaf(ef, s0.x, p0.x); s0.y = fmaf(ef, s0.y, p0.y);
        s0.z = fmaf(ef, s0.z, p0.z); s0.w = fmaf(ef, s0.w, p0.w);
        s1.x = fmaf(ef, s1.x, p1.x); s1.y = fmaf(ef, s1.y, p1.y);
        s1.z = fmaf(ef, s1.z, p1.z); s1.w = fmaf(ef, s1.w, p1.w);
    }
}

// ---------------- K_y: y = inter + intra, fused D_skip + z-gate -------------------
__global__ void __launch_bounds__(256) yout_kernel(const float* __restrict__ D_skip)
{
    const int bx = blockIdx.x;
    const int hh = bx & 15;
    const int cc = (bx >> 4) & (NCHUNK - 1);
    const int bb = bx >> 9;
    const int tid = threadIdx.x;
    const int t = tid >> 2;
    const int r = tid & 3;

    __shared__ __align__(16) float sX[256][16];
    __shared__ __align__(16) float sS[128][16];
    __shared__ float sLa[64], sDt[64];

    const int brow = bb * LL + cc * QC;
    {
        const int s = tid >> 2, q = tid & 3;
        const float4* src = (const float4*)(g_X + (size_t)(brow + s) * 1024 + hh * 64 + q * 16);
        float4* dst = (float4*)&sX[(s << 2) | q][0];
#pragma unroll
        for (int i = 0; i < 4; i++) dst[i] = src[i];
    }
    {
        const float4* src = (const float4*)(g_S + (size_t)bx * 2048 + tid * 8);
        float4* dst = (float4*)(&sS[0][0] + tid * 8);
        dst[0] = src[0]; dst[1] = src[1];
    }
    if (tid < 64) {
        sLa[tid] = g_La [((size_t)bb * 16 + hh) * LL + cc * QC + tid];
        sDt[tid] = g_dth[((size_t)bb * 16 + hh) * LL + cc * QC + tid];
    }
    __syncthreads();

    float acc[16];
#pragma unroll
    for (int i = 0; i < 16; i++) acc[i] = 0.f;

    // ---- inter-chunk: (Chat @ S_start) * exp(La[t]) ----
    const float4* crow = (const float4*)(g_CmT + (size_t)(brow + t) * 512 + r * 128);
    for (int nq = 0; nq < 32; nq++) {
        const float4 cv = __ldg(crow + nq);
#pragma unroll
        for (int j = 0; j < 4; j++) {
            const float cn = (j == 0) ? cv.x : (j == 1) ? cv.y : (j == 2) ? cv.z : cv.w;
            const float* sr = &sS[nq * 4 + j][0];
#pragma unroll
            for (int p = 0; p < 16; p++) acc[p] = fmaf(cn, sr[p], acc[p]);
        }
    }
    const float lat = sLa[t];
    const float einter = expf(lat);
#pragma unroll
    for (int p = 0; p < 16; p++) acc[p] *= einter;

    // ---- intra-chunk ----
    const float4* Gp = (const float4*)(g_G + (size_t)(bb * NCHUNK + cc) * 65536 + (size_t)tid * 256);
    for (int s = 0; s <= t; s++) {
        const float w = expf(lat - sLa[s]) * sDt[s];
        const float4 gv = __ldg(Gp + s);
        const float g0 = gv.x * w, g1 = gv.y * w, g2 = gv.z * w, g3 = gv.w * w;
        const float* x0 = &sX[s * 4 + 0][0];
        const float* x1 = &sX[s * 4 + 1][0];
        const float* x2 = &sX[s * 4 + 2][0];
        const float* x3 = &sX[s * 4 + 3][0];
#pragma unroll
        for (int p = 0; p < 16; p++) {
            float v = fmaf(g0, x0[p], acc[p]);
            v = fmaf(g1, x1[p], v);
            v = fmaf(g2, x2[p], v);
            acc[p] = fmaf(g3, x3[p], v);
        }
    }

    // ---- epilogue: + x*D_skip, gate with silu(z), write g_g ----
    const float dsk = D_skip[hh];
    const int row = brow + t;
    const float* xv = &sX[tid][0];
    float* go = g_g + (size_t)row * 1024 + hh * 64 + r * 16;
    const float* zp = g_zx + (size_t)row * 3088 + hh * 64 + r * 16;
#pragma unroll
    for (int p = 0; p < 16; p++) {
        const float y = fmaf(xv[p], dsk, acc[p]);
        const float z = zp[p];
        go[p] = y * (z / (1.f + expf(-z)));
    }
}

// ---------------- RMSNorm ---------------------------------------------------------
__global__ void __launch_bounds__(256) rms_kernel(float* __restrict__ out)
{
    const int warp = threadIdx.x >> 5;
    const int lane = threadIdx.x & 31;
    const int row  = blockIdx.x * 8 + warp;
    const float* r = g_res + (size_t)row * 512;
    float v[16];
    float ss = 0.f;
#pragma unroll
    for (int i = 0; i < 16; i++) { v[i] = r[lane + i * 32]; ss = fmaf(v[i], v[i], ss); }
#pragma unroll
    for (int o = 16; o >= 1; o >>= 1) ss += __shfl_xor_sync(0xffffffffu, ss, o);
    const float sc = rsqrtf(ss * (1.f / 512.f) + 1e-5f);
    float* o = out + (size_t)row * 512;
#pragma unroll
    for (int i = 0; i < 16; i++) o[lane + i * 32] = v[i] * sc;
}

// ---------------- launch ----------------------------------------------------------
extern "C" void kernel_launch(void* const* d_in, const int* in_sizes, int n_in,
                              void* d_out, int out_size)
{
    const float* hs      = (const float*)d_in[0];
    const float* W_in    = (const float*)d_in[1];
    const float* conv_w  = (const float*)d_in[2];
    const float* conv_b  = (const float*)d_in[3];
    const float* dt_bias = (const float*)d_in[4];
    const float* A_log   = (const float*)d_in[5];
    const float* D_skip  = (const float*)d_in[6];
    const float* W_out   = (const float*)d_in[7];
    float* out = (float*)d_out;

    gemm1_kernel<<<dim3(25, 64), 256>>>(hs, W_in);
    conv_kernel<<<NROWS * 2048 / 256, 256>>>(conv_w, conv_b);
    dt_kernel<<<NROWS * 16 / 256, 256>>>(dt_bias, A_log);
    cumsum_kernel<<<256, 256>>>();
    gscore_kernel<<<dim3(2, 2, 128), 256>>>();
    pstate_kernel<<<2048, 256>>>();
    carry_kernel<<<64, 256>>>();
    yout_kernel<<<2048, 256>>>(D_skip);
    gemm2_kernel<<<dim3(4, 64), 256>>>(W_out, hs);
    rms_kernel<<<NROWS / 8, 256>>>(out);
}